// round 3
// baseline (speedup 1.0000x reference)
#include <cuda_runtime.h>
#include <math.h>

#define NN 50000
#define NE 600000
#define DD 128
#define NND (NN * DD)
#define NT ((NN + 63) / 64)      // 782 GEMM tiles of 64 rows
#define AST 132                   // As row stride (floats)
#define BSL 130                   // Bs row stride (float2 pairs)
#define SMEM_BYTES (128 * BSL * 8 + 64 * AST * 4 + 128 * 4 + 16)

// ---------------- device scratch (static, zero-initialized) ----------------
__device__ int   g_is64;
__device__ int   g_counts[NN];
__device__ int   g_offsets[NN];
__device__ int   g_cursor[NN];
__device__ int   g_srcs[NE];
__device__ float g_yl[(size_t)NN * DD];          // x @ Wl.T  (25.6 MB)
__device__ unsigned g_total  = 0;                // offsets bump
__device__ unsigned g_tile   = 0;                // GEMM tile work-stealing
__device__ unsigned g_bar_cnt = 0;               // grid barrier (cumulative)
__device__ volatile unsigned g_bar_phase = 0;
__device__ unsigned g_bar_dep = 0;               // end-of-kernel depart
__device__ unsigned g_sub_cnt = 0;               // CSR-subset barrier
__device__ volatile unsigned g_sub_phase = 0;

__device__ __forceinline__ int ld_idx(const void* ei, long long pos, int is64) {
    return is64 ? (int)((const long long*)ei)[pos] : ((const int*)ei)[pos];
}

// cumulative-count grid barrier: use = 1,2,...  (all CTAs resident)
__device__ __forceinline__ void grid_barrier(unsigned use, unsigned ncta) {
    __syncthreads();
    if (threadIdx.x == 0) {
        __threadfence();
        unsigned n = atomicAdd(&g_bar_cnt, 1u);
        if (n == use * ncta - 1u) g_bar_phase = use;
        else while (g_bar_phase < use) __nanosleep(64);
        __threadfence();
    }
    __syncthreads();
}

__device__ __forceinline__ void sub_barrier(unsigned use, unsigned csrn) {
    __syncthreads();
    if (threadIdx.x == 0) {
        __threadfence();
        unsigned n = atomicAdd(&g_sub_cnt, 1u);
        if (n == use * csrn - 1u) g_sub_phase = use;
        else while (g_sub_phase < use) __nanosleep(64);
        __threadfence();
    }
    __syncthreads();
}

// ---------------- the persistent mega-kernel ----------------
__global__ void __launch_bounds__(256, 1)
k_mega(const float* __restrict__ x, const void* __restrict__ ei,
       const float* __restrict__ Wl, const float* __restrict__ bl,
       const float* __restrict__ Wr, float* __restrict__ out,
       int ncta, int csrn, int do_tail) {
    extern __shared__ char smraw[];
    float2* Bs   = (float2*)smraw;                              // [128][BSL]
    float*  As   = (float*)(smraw + 128 * BSL * 8);             // [64][AST]
    float*  bias = (float*)(smraw + 128 * BSL * 8 + 64 * AST * 4);
    int*    sm_t = (int*)(bias + 128);

    const int tid  = threadIdx.x;
    const int cta  = blockIdx.x;
    const int wid  = tid >> 5;
    const int lane = tid & 31;

    // ---- init phase: detect dtype, zero counts, fill Bs/bias ----
    if (cta == 0 && wid == 0) {
        const int* p = (const int*)ei;
        int v = p[lane * 2 + 1] | p[64 + lane * 2 + 1] |
                p[128 + lane * 2 + 1] | p[192 + lane * 2 + 1];
        unsigned any = __ballot_sync(0xffffffffu, v != 0);
        if (lane == 0) g_is64 = (any == 0u);
    }
    for (int i = cta * 256 + tid; i < NN; i += ncta * 256) g_counts[i] = 0;

    // Bs[k][q]     = (Wl[q][k],     Wl[q+64][k])   q in 0..63
    // Bs[k][64+q]  = (Wr[q][k],     Wr[q+64][k])
    for (int j = wid; j < 128; j += 8) {
        float4 vl = ((const float4*)(Wl + (size_t)j * DD))[lane];
        float4 vr = ((const float4*)(Wr + (size_t)j * DD))[lane];
        int q = j & 63, hl = j >> 6;
        int k = lane * 4;
        ((float*)&Bs[(k + 0) * BSL + q])[hl] = vl.x;
        ((float*)&Bs[(k + 1) * BSL + q])[hl] = vl.y;
        ((float*)&Bs[(k + 2) * BSL + q])[hl] = vl.z;
        ((float*)&Bs[(k + 3) * BSL + q])[hl] = vl.w;
        ((float*)&Bs[(k + 0) * BSL + 64 + q])[hl] = vr.x;
        ((float*)&Bs[(k + 1) * BSL + 64 + q])[hl] = vr.y;
        ((float*)&Bs[(k + 2) * BSL + 64 + q])[hl] = vr.z;
        ((float*)&Bs[(k + 3) * BSL + 64 + q])[hl] = vr.w;
    }
    if (tid < 128) bias[tid] = bl[tid];

    grid_barrier(1, ncta);
    const int is64 = g_is64;

    // ---- CSR build on csrn CTAs (others go straight to GEMM) ----
    if (cta < csrn) {
        const int step = csrn * 256;
        const int tg = cta * 256 + tid;
        for (int e = tg; e < NE; e += step)
            atomicAdd(&g_counts[ld_idx(ei, (long long)NE + e, is64)], 1);
        sub_barrier(1, (unsigned)csrn);
        // offsets: warp-aggregated bump (bucket order irrelevant)
        for (int wb = cta * 256 + wid * 32; wb < NN; wb += step) {
            int i = wb + lane;
            int c = (i < NN) ? g_counts[i] : 0;
            int s = c;
            #pragma unroll
            for (int off = 1; off < 32; off <<= 1) {
                int v = __shfl_up_sync(0xffffffffu, s, off);
                if (lane >= off) s += v;
            }
            int tot = __shfl_sync(0xffffffffu, s, 31);
            unsigned base = 0;
            if (lane == 31) base = atomicAdd(&g_total, (unsigned)tot);
            base = __shfl_sync(0xffffffffu, base, 31);
            int excl = (int)base + s - c;
            if (i < NN) { g_offsets[i] = excl; g_cursor[i] = excl; }
        }
        sub_barrier(2, (unsigned)csrn);
        for (int e = tg; e < NE; e += step) {
            int src = ld_idx(ei, e, is64);
            int dst = ld_idx(ei, (long long)NE + e, is64);
            int p = atomicAdd(&g_cursor[dst], 1);
            g_srcs[p] = src;
        }
    }

    // ---- GEMM: y_l = x@Wl.T -> g_yl ; y_r = x@Wr.T + b -> out ----
    // 64-row tiles, work-stealing. 256 thr: 4 rows x 8 col-pairs each.
    {
        const int tm0 = (tid >> 4) * 4;
        const int c0  = tid & 15;
        for (;;) {
            __syncthreads();
            if (tid == 0) *sm_t = (int)atomicAdd(&g_tile, 1u);
            __syncthreads();
            int t = *sm_t;
            if (t >= NT) break;
            int row0 = t * 64;
            // stage As = x[row0:row0+64, :]
            {
                int m = tid >> 2, seg = tid & 3;
                int gr = row0 + m;
                const float4* src = (const float4*)(x + (size_t)gr * DD + seg * 32);
                #pragma unroll
                for (int u = 0; u < 8; u++) {
                    float4 w = (gr < NN) ? src[u]
                                         : make_float4(0.f, 0.f, 0.f, 0.f);
                    int c = seg * 32 + u * 4;
                    As[m * AST + c + 0] = w.x;
                    As[m * AST + c + 1] = w.y;
                    As[m * AST + c + 2] = w.z;
                    As[m * AST + c + 3] = w.w;
                }
            }
            __syncthreads();

            unsigned long long acc[4][8];
            #pragma unroll
            for (int i = 0; i < 4; i++)
                #pragma unroll
                for (int j = 0; j < 8; j++) acc[i][j] = 0ull;

            #pragma unroll 4
            for (int kk = 0; kk < 128; kk++) {
                unsigned long long a2[4], b2[8];
                #pragma unroll
                for (int i = 0; i < 4; i++) {
                    float a = As[(tm0 + i) * AST + kk];
                    asm("mov.b64 %0, {%1, %1};" : "=l"(a2[i]) : "f"(a));
                }
                #pragma unroll
                for (int j = 0; j < 8; j++)
                    b2[j] = *(const unsigned long long*)
                            &Bs[kk * BSL + (j >> 2) * 64 + c0 + 16 * (j & 3)];
                #pragma unroll
                for (int i = 0; i < 4; i++)
                    #pragma unroll
                    for (int j = 0; j < 8; j++)
                        asm("fma.rn.f32x2 %0, %1, %2, %0;"
                            : "+l"(acc[i][j]) : "l"(a2[i]), "l"(b2[j]));
            }

            // epilogue: j<4 -> y_l (g_yl), j>=4 -> y_r (+bias) into out
            #pragma unroll
            for (int i = 0; i < 4; i++) {
                int r = row0 + tm0 + i;
                if (r < NN) {
                    #pragma unroll
                    for (int j = 0; j < 8; j++) {
                        float2 v = *(float2*)&acc[i][j];
                        int q = c0 + 16 * (j & 3);
                        if (j < 4) {
                            g_yl[(size_t)r * DD + q]      = v.x;
                            g_yl[(size_t)r * DD + q + 64] = v.y;
                        } else {
                            out[(size_t)r * DD + q]      = v.x + bias[q];
                            out[(size_t)r * DD + q + 64] = v.y + bias[q + 64];
                        }
                    }
                }
            }
        }
    }

    grid_barrier(2, ncta);

    // ---- aggregate: out = ELU(mean(y_l[src]) + y_r), warp per node ----
    {
        const int warps = ncta * 8;
        const float4* yv = (const float4*)g_yl;
        for (int node = cta * 8 + wid; node < NN; node += warps) {
            int start = g_offsets[node];
            int cnt   = g_counts[node];
            float4 a = make_float4(0.f, 0.f, 0.f, 0.f);
            int i = 0;
            for (; i + 3 < cnt; i += 4) {
                int s0 = g_srcs[start + i];
                int s1 = g_srcs[start + i + 1];
                int s2 = g_srcs[start + i + 2];
                int s3 = g_srcs[start + i + 3];
                float4 v0 = __ldg(&yv[(size_t)s0 * 32 + lane]);
                float4 v1 = __ldg(&yv[(size_t)s1 * 32 + lane]);
                float4 v2 = __ldg(&yv[(size_t)s2 * 32 + lane]);
                float4 v3 = __ldg(&yv[(size_t)s3 * 32 + lane]);
                a.x += (v0.x + v1.x) + (v2.x + v3.x);
                a.y += (v0.y + v1.y) + (v2.y + v3.y);
                a.z += (v0.z + v1.z) + (v2.z + v3.z);
                a.w += (v0.w + v1.w) + (v2.w + v3.w);
            }
            for (; i < cnt; i++) {
                int s0 = g_srcs[start + i];
                float4 v0 = __ldg(&yv[(size_t)s0 * 32 + lane]);
                a.x += v0.x; a.y += v0.y; a.z += v0.z; a.w += v0.w;
            }
            float inv = 1.0f / fmaxf((float)cnt, 1.0f);
            float4* orow = (float4*)(out + (size_t)node * DD);
            float4 yr = orow[lane];
            float ox = a.x * inv + yr.x;
            float oy = a.y * inv + yr.y;
            float oz = a.z * inv + yr.z;
            float ow = a.w * inv + yr.w;
            ox = (ox > 0.f) ? ox : expm1f(ox);
            oy = (oy > 0.f) ? oy : expm1f(oy);
            oz = (oz > 0.f) ? oz : expm1f(oz);
            ow = (ow > 0.f) ? ow : expm1f(ow);
            orow[lane] = make_float4(ox, oy, oz, ow);
        }
    }

    // ---- tail: edge_index passthrough ----
    if (do_tail) {
        for (int t = cta * 256 + tid; t < 2 * NE; t += ncta * 256)
            out[NND + t] = (float)ld_idx(ei, t, is64);
    }

    // ---- depart: last CTA out resets all cross-launch state ----
    __syncthreads();
    if (tid == 0) {
        __threadfence();
        unsigned d = atomicAdd(&g_bar_dep, 1u);
        if (d == (unsigned)ncta - 1u) {
            g_bar_cnt = 0; g_bar_phase = 0; g_bar_dep = 0;
            g_sub_cnt = 0; g_sub_phase = 0;
            g_tile = 0;    g_total = 0;
        }
    }
}

// ---------------- launch ----------------
extern "C" void kernel_launch(void* const* d_in, const int* in_sizes, int n_in,
                              void* d_out, int out_size) {
    const float* x  = (const float*)d_in[0];
    const void*  ei = d_in[1];
    const float* Wl = (const float*)d_in[2];
    const float* bl = (const float*)d_in[3];
    const float* Wr = (const float*)d_in[4];
    float* out = (float*)d_out;

    int dev = 0;
    cudaGetDevice(&dev);
    int ncta = 0;
    cudaDeviceGetAttribute(&ncta, cudaDevAttrMultiProcessorCount, dev);
    if (ncta <= 0) ncta = 148;
    int csrn = ncta / 4;
    if (csrn < 1) csrn = 1;
    int do_tail = (out_size >= NND + 2 * NE) ? 1 : 0;

    cudaFuncSetAttribute(k_mega, cudaFuncAttributeMaxDynamicSharedMemorySize,
                         SMEM_BYTES);
    k_mega<<<ncta, 256, SMEM_BYTES>>>(x, ei, Wl, bl, Wr, out,
                                      ncta, csrn, do_tail);
}

// round 4
// speedup vs baseline: 1.1152x; 1.1152x over previous
#include <cuda_runtime.h>
#include <math.h>

#define NN 50000
#define NE 600000
#define DD 128
#define NND (NN * DD)
#define TROWS 128
#define NT ((NN + TROWS - 1) / TROWS)   // 391 GEMM tiles of 128 rows
#define AST 132                          // As row stride (floats)
#define BSL 130                          // Bs row stride (float2 pairs)
#define NTHR 512
#define SMEM_BYTES (128 * BSL * 8 + TROWS * AST * 4 + 128 * 4 + 16)

// ---------------- device scratch (static, zero-initialized) ----------------
__device__ int   g_is64;
__device__ int   g_counts[NN];
__device__ int   g_offsets[NN];
__device__ int   g_cursor[NN];
__device__ int   g_srcs[NE];
__device__ float g_yl[(size_t)NN * DD];          // x @ Wl.T  (25.6 MB)
__device__ unsigned g_total  = 0;                // offsets bump
__device__ unsigned g_tile   = 0;                // GEMM tile work-stealing
__device__ unsigned g_bar_cnt = 0;               // grid barrier (cumulative)
__device__ volatile unsigned g_bar_phase = 0;
__device__ unsigned g_bar_dep = 0;               // end-of-kernel depart
__device__ unsigned g_sub_cnt = 0;               // CSR-subset barrier
__device__ volatile unsigned g_sub_phase = 0;

__device__ __forceinline__ int ld_idx(const void* ei, long long pos, int is64) {
    return is64 ? (int)((const long long*)ei)[pos] : ((const int*)ei)[pos];
}

// cumulative-count grid barrier: use = 1,2,...  (all CTAs resident)
__device__ __forceinline__ void grid_barrier(unsigned use, unsigned ncta) {
    __syncthreads();
    if (threadIdx.x == 0) {
        __threadfence();
        unsigned n = atomicAdd(&g_bar_cnt, 1u);
        if (n == use * ncta - 1u) g_bar_phase = use;
        else while (g_bar_phase < use) __nanosleep(64);
        __threadfence();
    }
    __syncthreads();
}

__device__ __forceinline__ void sub_barrier(unsigned use, unsigned csrn) {
    __syncthreads();
    if (threadIdx.x == 0) {
        __threadfence();
        unsigned n = atomicAdd(&g_sub_cnt, 1u);
        if (n == use * csrn - 1u) g_sub_phase = use;
        else while (g_sub_phase < use) __nanosleep(64);
        __threadfence();
    }
    __syncthreads();
}

// ---------------- the persistent mega-kernel ----------------
__global__ void __launch_bounds__(NTHR, 1)
k_mega(const float* __restrict__ x, const void* __restrict__ ei,
       const float* __restrict__ Wl, const float* __restrict__ bl,
       const float* __restrict__ Wr, float* __restrict__ out,
       int ncta, int csrn, int do_tail) {
    extern __shared__ char smraw[];
    float2* Bs   = (float2*)smraw;                              // [128][BSL]
    float*  As   = (float*)(smraw + 128 * BSL * 8);             // [TROWS][AST]
    float*  bias = (float*)(smraw + 128 * BSL * 8 + TROWS * AST * 4);
    int*    sm_t = (int*)(bias + 128);

    const int tid  = threadIdx.x;
    const int cta  = blockIdx.x;
    const int wid  = tid >> 5;       // 0..15
    const int lane = tid & 31;

    // ---- init phase: detect dtype, zero counts, fill Bs/bias ----
    if (cta == 0 && wid == 0) {
        const int* p = (const int*)ei;
        int v = p[lane * 2 + 1] | p[64 + lane * 2 + 1] |
                p[128 + lane * 2 + 1] | p[192 + lane * 2 + 1];
        unsigned any = __ballot_sync(0xffffffffu, v != 0);
        if (lane == 0) g_is64 = (any == 0u);
    }
    for (int i = cta * NTHR + tid; i < NN; i += ncta * NTHR) g_counts[i] = 0;

    // Bs[k][q]     = (Wl[q][k],     Wl[q+64][k])   q in 0..63
    // Bs[k][64+q]  = (Wr[q][k],     Wr[q+64][k])
    for (int j = wid; j < 128; j += 16) {
        float4 vl = ((const float4*)(Wl + (size_t)j * DD))[lane];
        float4 vr = ((const float4*)(Wr + (size_t)j * DD))[lane];
        int q = j & 63, hl = j >> 6;
        int k = lane * 4;
        ((float*)&Bs[(k + 0) * BSL + q])[hl] = vl.x;
        ((float*)&Bs[(k + 1) * BSL + q])[hl] = vl.y;
        ((float*)&Bs[(k + 2) * BSL + q])[hl] = vl.z;
        ((float*)&Bs[(k + 3) * BSL + q])[hl] = vl.w;
        ((float*)&Bs[(k + 0) * BSL + 64 + q])[hl] = vr.x;
        ((float*)&Bs[(k + 1) * BSL + 64 + q])[hl] = vr.y;
        ((float*)&Bs[(k + 2) * BSL + 64 + q])[hl] = vr.z;
        ((float*)&Bs[(k + 3) * BSL + 64 + q])[hl] = vr.w;
    }
    if (tid < 128) bias[tid] = bl[tid];

    grid_barrier(1, ncta);
    const int is64 = g_is64;

    // ---- CSR build on csrn CTAs (others go straight to GEMM) ----
    if (cta < csrn) {
        const int step = csrn * NTHR;
        const int tg = cta * NTHR + tid;
        for (int e = tg; e < NE; e += step)
            atomicAdd(&g_counts[ld_idx(ei, (long long)NE + e, is64)], 1);
        sub_barrier(1, (unsigned)csrn);
        // offsets: warp-aggregated bump (bucket order irrelevant)
        for (int wb = cta * NTHR + wid * 32; wb < NN; wb += step) {
            int i = wb + lane;
            int c = (i < NN) ? g_counts[i] : 0;
            int s = c;
            #pragma unroll
            for (int off = 1; off < 32; off <<= 1) {
                int v = __shfl_up_sync(0xffffffffu, s, off);
                if (lane >= off) s += v;
            }
            int tot = __shfl_sync(0xffffffffu, s, 31);
            unsigned base = 0;
            if (lane == 31) base = atomicAdd(&g_total, (unsigned)tot);
            base = __shfl_sync(0xffffffffu, base, 31);
            int excl = (int)base + s - c;
            if (i < NN) { g_offsets[i] = excl; g_cursor[i] = excl; }
        }
        sub_barrier(2, (unsigned)csrn);
        for (int e = tg; e < NE; e += step) {
            int src = ld_idx(ei, e, is64);
            int dst = ld_idx(ei, (long long)NE + e, is64);
            int p = atomicAdd(&g_cursor[dst], 1);
            g_srcs[p] = src;
        }
    }

    // ---- GEMM: y_l = x@Wl.T -> g_yl ; y_r = x@Wr.T + b -> out ----
    // 128-row tiles, work-stealing. 512 thr: 4 rows x 8 col-pairs each.
    {
        const int tm0 = (tid >> 4) * 4;   // 0..124
        const int c0  = tid & 15;
        for (;;) {
            __syncthreads();
            if (tid == 0) *sm_t = (int)atomicAdd(&g_tile, 1u);
            __syncthreads();
            int t = *sm_t;
            if (t >= NT) break;
            int row0 = t * TROWS;
            // stage As = x[row0:row0+128, :]  (32 floats per thread)
            {
                int m = tid >> 2, seg = tid & 3;
                int gr = row0 + m;
                const float4* src = (const float4*)(x + (size_t)gr * DD + seg * 32);
                #pragma unroll
                for (int u = 0; u < 8; u++) {
                    float4 w = (gr < NN) ? src[u]
                                         : make_float4(0.f, 0.f, 0.f, 0.f);
                    int c = seg * 32 + u * 4;
                    As[m * AST + c + 0] = w.x;
                    As[m * AST + c + 1] = w.y;
                    As[m * AST + c + 2] = w.z;
                    As[m * AST + c + 3] = w.w;
                }
            }
            __syncthreads();

            unsigned long long acc[4][8];
            #pragma unroll
            for (int i = 0; i < 4; i++)
                #pragma unroll
                for (int j = 0; j < 8; j++) acc[i][j] = 0ull;

            #pragma unroll 4
            for (int kk = 0; kk < 128; kk++) {
                unsigned long long a2[4], b2[8];
                #pragma unroll
                for (int i = 0; i < 4; i++) {
                    float a = As[(tm0 + i) * AST + kk];
                    asm("mov.b64 %0, {%1, %1};" : "=l"(a2[i]) : "f"(a));
                }
                #pragma unroll
                for (int j = 0; j < 8; j++)
                    b2[j] = *(const unsigned long long*)
                            &Bs[kk * BSL + (j >> 2) * 64 + c0 + 16 * (j & 3)];
                #pragma unroll
                for (int i = 0; i < 4; i++)
                    #pragma unroll
                    for (int j = 0; j < 8; j++)
                        asm("fma.rn.f32x2 %0, %1, %2, %0;"
                            : "+l"(acc[i][j]) : "l"(a2[i]), "l"(b2[j]));
            }

            // epilogue: j<4 -> y_l (g_yl), j>=4 -> y_r (+bias) into out
            #pragma unroll
            for (int i = 0; i < 4; i++) {
                int r = row0 + tm0 + i;
                if (r < NN) {
                    #pragma unroll
                    for (int j = 0; j < 8; j++) {
                        float2 v = *(float2*)&acc[i][j];
                        int q = c0 + 16 * (j & 3);
                        if (j < 4) {
                            g_yl[(size_t)r * DD + q]      = v.x;
                            g_yl[(size_t)r * DD + q + 64] = v.y;
                        } else {
                            out[(size_t)r * DD + q]      = v.x + bias[q];
                            out[(size_t)r * DD + q + 64] = v.y + bias[q + 64];
                        }
                    }
                }
            }
        }
    }

    grid_barrier(2, ncta);

    // ---- aggregate: out = ELU(mean(y_l[src]) + y_r), warp per node ----
    {
        const int warps = ncta * 16;
        const float4* yv = (const float4*)g_yl;
        for (int node = cta * 16 + wid; node < NN; node += warps) {
            int start = g_offsets[node];
            int cnt   = g_counts[node];
            float4 a = make_float4(0.f, 0.f, 0.f, 0.f);
            int i = 0;
            for (; i + 3 < cnt; i += 4) {
                int s0 = g_srcs[start + i];
                int s1 = g_srcs[start + i + 1];
                int s2 = g_srcs[start + i + 2];
                int s3 = g_srcs[start + i + 3];
                float4 v0 = __ldg(&yv[(size_t)s0 * 32 + lane]);
                float4 v1 = __ldg(&yv[(size_t)s1 * 32 + lane]);
                float4 v2 = __ldg(&yv[(size_t)s2 * 32 + lane]);
                float4 v3 = __ldg(&yv[(size_t)s3 * 32 + lane]);
                a.x += (v0.x + v1.x) + (v2.x + v3.x);
                a.y += (v0.y + v1.y) + (v2.y + v3.y);
                a.z += (v0.z + v1.z) + (v2.z + v3.z);
                a.w += (v0.w + v1.w) + (v2.w + v3.w);
            }
            for (; i < cnt; i++) {
                int s0 = g_srcs[start + i];
                float4 v0 = __ldg(&yv[(size_t)s0 * 32 + lane]);
                a.x += v0.x; a.y += v0.y; a.z += v0.z; a.w += v0.w;
            }
            float inv = 1.0f / fmaxf((float)cnt, 1.0f);
            float4* orow = (float4*)(out + (size_t)node * DD);
            float4 yr = orow[lane];
            float ox = a.x * inv + yr.x;
            float oy = a.y * inv + yr.y;
            float oz = a.z * inv + yr.z;
            float ow = a.w * inv + yr.w;
            ox = (ox > 0.f) ? ox : expm1f(ox);
            oy = (oy > 0.f) ? oy : expm1f(oy);
            oz = (oz > 0.f) ? oz : expm1f(oz);
            ow = (ow > 0.f) ? ow : expm1f(ow);
            orow[lane] = make_float4(ox, oy, oz, ow);
        }
    }

    // ---- tail: edge_index passthrough ----
    if (do_tail) {
        for (int t = cta * NTHR + tid; t < 2 * NE; t += ncta * NTHR)
            out[NND + t] = (float)ld_idx(ei, t, is64);
    }

    // ---- depart: last CTA out resets all cross-launch state ----
    __syncthreads();
    if (tid == 0) {
        __threadfence();
        unsigned d = atomicAdd(&g_bar_dep, 1u);
        if (d == (unsigned)ncta - 1u) {
            g_bar_cnt = 0; g_bar_phase = 0; g_bar_dep = 0;
            g_sub_cnt = 0; g_sub_phase = 0;
            g_tile = 0;    g_total = 0;
        }
    }
}

// ---------------- launch ----------------
extern "C" void kernel_launch(void* const* d_in, const int* in_sizes, int n_in,
                              void* d_out, int out_size) {
    const float* x  = (const float*)d_in[0];
    const void*  ei = d_in[1];
    const float* Wl = (const float*)d_in[2];
    const float* bl = (const float*)d_in[3];
    const float* Wr = (const float*)d_in[4];
    float* out = (float*)d_out;

    int dev = 0;
    cudaGetDevice(&dev);
    int ncta = 0;
    cudaDeviceGetAttribute(&ncta, cudaDevAttrMultiProcessorCount, dev);
    if (ncta <= 0) ncta = 148;
    int csrn = ncta / 4;
    if (csrn < 1) csrn = 1;
    int do_tail = (out_size >= NND + 2 * NE) ? 1 : 0;

    cudaFuncSetAttribute(k_mega, cudaFuncAttributeMaxDynamicSharedMemorySize,
                         SMEM_BYTES);
    k_mega<<<ncta, NTHR, SMEM_BYTES>>>(x, ei, Wl, bl, Wr, out,
                                       ncta, csrn, do_tail);
}

// round 6
// speedup vs baseline: 1.3183x; 1.1822x over previous
#include <cuda_runtime.h>
#include <cuda_bf16.h>
#include <math.h>
#include <stdint.h>

#define NN 50000
#define NE 600000
#define DD 128
#define NND (NN * DD)
#define TROWS 128
#define NT ((NN + TROWS - 1) / TROWS)   // 391 tiles
#define NTHR 512
#define RSTR 272                         // smem row stride in bytes (17*16)

// ---- smem byte offsets ----
#define SM_BH   0                        // B-hi: 256 rows x 272B
#define SM_BL   69632                    // B-lo
#define SM_AH   139264                   // A-hi: 128 rows x 272B
#define SM_AL   174080                   // A-lo
#define SM_BIAS 208896                   // 128 floats
#define SM_T    209408
#define SMEM_BYTES 209424

// ---------------- device scratch ----------------
__device__ int   g_is64;
__device__ int   g_counts[NN];
__device__ int   g_offsets[NN];
__device__ int   g_cursor[NN];
__device__ int   g_srcs[NE];
__device__ float g_yl[(size_t)NN * DD];          // x @ Wl.T  (25.6 MB)
__device__ unsigned g_total   = 0;
__device__ unsigned g_tile    = 0;
__device__ unsigned g_bar_cnt = 0;
__device__ volatile unsigned g_bar_phase = 0;
__device__ unsigned g_bar_dep = 0;
__device__ unsigned g_sub_cnt = 0;
__device__ volatile unsigned g_sub_phase = 0;

// ---------------- helpers ----------------
__device__ __forceinline__ uint32_t s2u(const void* p) {
    uint32_t a;
    asm("{ .reg .u64 t; cvta.to.shared.u64 t, %1; cvt.u32.u64 %0, t; }"
        : "=r"(a) : "l"(p));
    return a;
}
__device__ __forceinline__ void ldsm4(uint32_t* r, uint32_t addr) {
    asm volatile("ldmatrix.sync.aligned.m8n8.x4.shared.b16 {%0,%1,%2,%3}, [%4];"
        : "=r"(r[0]), "=r"(r[1]), "=r"(r[2]), "=r"(r[3]) : "r"(addr));
}
__device__ __forceinline__ void mma_bf16(float* c, const uint32_t* a,
                                         const uint32_t* b) {
    asm volatile("mma.sync.aligned.m16n8k16.row.col.f32.bf16.bf16.f32 "
        "{%0,%1,%2,%3}, {%4,%5,%6,%7}, {%8,%9}, {%0,%1,%2,%3};"
        : "+f"(c[0]), "+f"(c[1]), "+f"(c[2]), "+f"(c[3])
        : "r"(a[0]), "r"(a[1]), "r"(a[2]), "r"(a[3]), "r"(b[0]), "r"(b[1]));
}
__device__ __forceinline__ int ld_idx(const void* ei, long long pos, int is64) {
    return is64 ? (int)((const long long*)ei)[pos] : ((const int*)ei)[pos];
}
__device__ __forceinline__ uint32_t packbf(float a, float b) {
    uint32_t r;
    asm("cvt.rn.satfinite.bf16x2.f32 %0, %1, %2;" : "=r"(r) : "f"(b), "f"(a));
    return r;
}
// split 2 consecutive f32 into packed bf16 hi pair + lo (residual) pair
__device__ __forceinline__ void split2(float f0, float f1, uint32_t& h, uint32_t& l) {
    __nv_bfloat16 h0 = __float2bfloat16_rn(f0);
    __nv_bfloat16 h1 = __float2bfloat16_rn(f1);
    float r0 = f0 - __bfloat162float(h0);
    float r1 = f1 - __bfloat162float(h1);
    h = ((uint32_t)__bfloat16_as_ushort(h1) << 16) | __bfloat16_as_ushort(h0);
    l = packbf(r0, r1);
}

__device__ __forceinline__ void grid_barrier(unsigned use, unsigned ncta) {
    __syncthreads();
    if (threadIdx.x == 0) {
        __threadfence();
        unsigned n = atomicAdd(&g_bar_cnt, 1u);
        if (n == use * ncta - 1u) g_bar_phase = use;
        else while (g_bar_phase < use) __nanosleep(64);
        __threadfence();
    }
    __syncthreads();
}
__device__ __forceinline__ void sub_barrier(unsigned use, unsigned csrn) {
    __syncthreads();
    if (threadIdx.x == 0) {
        __threadfence();
        unsigned n = atomicAdd(&g_sub_cnt, 1u);
        if (n == use * csrn - 1u) g_sub_phase = use;
        else while (g_sub_phase < use) __nanosleep(64);
        __threadfence();
    }
    __syncthreads();
}

// ---------------- the persistent mega-kernel ----------------
__global__ void __launch_bounds__(NTHR, 1)
k_mega(const float* __restrict__ x, const void* __restrict__ ei,
       const float* __restrict__ Wl, const float* __restrict__ bl,
       const float* __restrict__ Wr, float* __restrict__ out,
       int ncta, int csrn, int do_tail) {
    extern __shared__ char sm[];
    const uint32_t sb = s2u(sm);
    float* bias = (float*)(sm + SM_BIAS);
    volatile int* sm_t = (volatile int*)(sm + SM_T);

    const int tid  = threadIdx.x;
    const int cta  = blockIdx.x;
    const int wid  = tid >> 5;
    const int lane = tid & 31;

    // ---- init: dtype detect, zero counts ----
    if (cta == 0 && wid == 0) {
        const int* p = (const int*)ei;
        int v = p[lane * 2 + 1] | p[64 + lane * 2 + 1] |
                p[128 + lane * 2 + 1] | p[192 + lane * 2 + 1];
        unsigned any = __ballot_sync(0xffffffffu, v != 0);
        if (lane == 0) g_is64 = (any == 0u);
    }
    for (int i = cta * NTHR + tid; i < NN; i += ncta * NTHR) g_counts[i] = 0;

    // ---- stage B = [Wl;Wr] split hi/lo bf16, [n][k] k-contig, stride 272B ----
    {
        int n = tid & 255, kh = tid >> 8;      // kh: 0/1 -> k 0..63 / 64..127
        const float* wrow = ((n < 128) ? (Wl + (size_t)n * DD)
                                       : (Wr + (size_t)(n - 128) * DD)) + kh * 64;
        char* bh = sm + SM_BH + n * RSTR + kh * 128;
        char* blo = sm + SM_BL + n * RSTR + kh * 128;
        #pragma unroll
        for (int u = 0; u < 8; u++) {
            float4 v0 = *(const float4*)(wrow + u * 8);
            float4 v1 = *(const float4*)(wrow + u * 8 + 4);
            uint4 hh, ll;
            split2(v0.x, v0.y, hh.x, ll.x);
            split2(v0.z, v0.w, hh.y, ll.y);
            split2(v1.x, v1.y, hh.z, ll.z);
            split2(v1.z, v1.w, hh.w, ll.w);
            *(uint4*)(bh + u * 16) = hh;
            *(uint4*)(blo + u * 16) = ll;
        }
    }
    if (tid < 128) bias[tid] = bl[tid];

    grid_barrier(1, ncta);
    const int is64 = g_is64;

    // ---- CSR build on csrn CTAs ----
    if (cta < csrn) {
        const int step = csrn * NTHR;
        const int tg = cta * NTHR + tid;
        for (int e = tg; e < NE; e += step)
            atomicAdd(&g_counts[ld_idx(ei, (long long)NE + e, is64)], 1);
        sub_barrier(1, (unsigned)csrn);
        for (int wb = cta * NTHR + wid * 32; wb < NN; wb += step) {
            int i = wb + lane;
            int c = (i < NN) ? g_counts[i] : 0;
            int s = c;
            #pragma unroll
            for (int off = 1; off < 32; off <<= 1) {
                int v = __shfl_up_sync(0xffffffffu, s, off);
                if (lane >= off) s += v;
            }
            int tot = __shfl_sync(0xffffffffu, s, 31);
            unsigned base = 0;
            if (lane == 31) base = atomicAdd(&g_total, (unsigned)tot);
            base = __shfl_sync(0xffffffffu, base, 31);
            int excl = (int)base + s - c;
            if (i < NN) { g_offsets[i] = excl; g_cursor[i] = excl; }
        }
        sub_barrier(2, (unsigned)csrn);
        for (int e = tg; e < NE; e += step) {
            int src = ld_idx(ei, e, is64);
            int dst = ld_idx(ei, (long long)NE + e, is64);
            int p = atomicAdd(&g_cursor[dst], 1);
            g_srcs[p] = src;
        }
    }

    // ---- GEMM: D[128,256] = x_tile @ [Wl;Wr]^T via mma.sync bf16 3-split ----
    // warp tile m32 x n64: mw = (wid&3)*32, nw = (wid>>2)*64
    {
        const int mw = (wid & 3) * 32;
        const int nw = (wid >> 2) * 64;
        const int g = lane >> 3, r = lane & 7;
        const uint32_t aoff = (uint32_t)((mw + r + (g & 1) * 8) * RSTR + (g >> 1) * 16);
        const uint32_t boff = (uint32_t)((nw + r + (g >> 1) * 8) * RSTR + (g & 1) * 16);
        const int tr = lane >> 2;            // 0..7
        const int tc = (lane & 3) * 2;

        for (;;) {
            __syncthreads();
            if (tid == 0) *sm_t = (int)atomicAdd(&g_tile, 1u);
            __syncthreads();
            int t = *sm_t;
            if (t >= NT) break;
            int row0 = t * TROWS;

            // stage A tile: m = tid&127, k-quarter = tid>>7 (32 k values)
            {
                int m = tid & 127, seg = tid >> 7;
                int gr = row0 + m;
                const float* xrow = x + (size_t)gr * DD + seg * 32;
                char* ah = sm + SM_AH + m * RSTR + seg * 64;
                char* al = sm + SM_AL + m * RSTR + seg * 64;
                #pragma unroll
                for (int u = 0; u < 4; u++) {
                    float4 v0, v1;
                    if (gr < NN) {
                        v0 = *(const float4*)(xrow + u * 8);
                        v1 = *(const float4*)(xrow + u * 8 + 4);
                    } else {
                        v0 = make_float4(0.f, 0.f, 0.f, 0.f); v1 = v0;
                    }
                    uint4 hh, ll;
                    split2(v0.x, v0.y, hh.x, ll.x);
                    split2(v0.z, v0.w, hh.y, ll.y);
                    split2(v1.x, v1.y, hh.z, ll.z);
                    split2(v1.z, v1.w, hh.w, ll.w);
                    *(uint4*)(ah + u * 16) = hh;
                    *(uint4*)(al + u * 16) = ll;
                }
            }
            __syncthreads();

            float acc[2][8][4];
            #pragma unroll
            for (int mi = 0; mi < 2; mi++)
                #pragma unroll
                for (int ni = 0; ni < 8; ni++)
                    #pragma unroll
                    for (int q = 0; q < 4; q++) acc[mi][ni][q] = 0.f;

            #pragma unroll 1
            for (int s = 0; s < 3; s++) {
                // s=0: Ah*Bh, s=1: Ah*Bl, s=2: Al*Bh
                uint32_t abase = sb + (s == 2 ? SM_AL : SM_AH) + aoff;
                uint32_t bbase = sb + (s == 1 ? SM_BL : SM_BH) + boff;
                #pragma unroll
                for (int k = 0; k < 8; k++) {
                    uint32_t a[2][4], b[4][4];
                    ldsm4(a[0], abase + k * 32);
                    ldsm4(a[1], abase + 16 * RSTR + k * 32);
                    #pragma unroll
                    for (int bg = 0; bg < 4; bg++)
                        ldsm4(b[bg], bbase + bg * 16 * RSTR + k * 32);
                    #pragma unroll
                    for (int mi = 0; mi < 2; mi++)
                        #pragma unroll
                        for (int ni = 0; ni < 8; ni++)
                            mma_bf16(acc[mi][ni], a[mi], &b[ni >> 1][(ni & 1) * 2]);
                }
            }

            // epilogue: nw<128 -> g_yl ; nw>=128 -> out + bias
            #pragma unroll
            for (int mi = 0; mi < 2; mi++) {
                #pragma unroll
                for (int rr = 0; rr < 2; rr++) {
                    int row = row0 + mw + mi * 16 + tr + rr * 8;
                    if (row < NN) {
                        if (nw < 128) {
                            float* dst = g_yl + (size_t)row * DD + nw + tc;
                            #pragma unroll
                            for (int ni = 0; ni < 8; ni++) {
                                float2 v = make_float2(acc[mi][ni][rr * 2],
                                                       acc[mi][ni][rr * 2 + 1]);
                                *(float2*)(dst + ni * 8) = v;
                            }
                        } else {
                            int j0 = nw - 128 + tc;
                            float* dst = out + (size_t)row * DD + j0;
                            #pragma unroll
                            for (int ni = 0; ni < 8; ni++) {
                                float2 v = make_float2(
                                    acc[mi][ni][rr * 2]     + bias[j0 + ni * 8],
                                    acc[mi][ni][rr * 2 + 1] + bias[j0 + ni * 8 + 1]);
                                *(float2*)(dst + ni * 8) = v;
                            }
                        }
                    }
                }
            }
        }
    }

    grid_barrier(2, ncta);

    // ---- aggregate: out = ELU(mean(y_l[src]) + y_r), warp per node ----
    {
        const int warps = ncta * 16;
        const float4* yv = (const float4*)g_yl;
        for (int node = cta * 16 + wid; node < NN; node += warps) {
            int start = g_offsets[node];
            int cnt   = g_counts[node];
            float4 a = make_float4(0.f, 0.f, 0.f, 0.f);
            int i = 0;
            for (; i + 3 < cnt; i += 4) {
                int s0 = g_srcs[start + i];
                int s1 = g_srcs[start + i + 1];
                int s2 = g_srcs[start + i + 2];
                int s3 = g_srcs[start + i + 3];
                float4 v0 = __ldg(&yv[(size_t)s0 * 32 + lane]);
                float4 v1 = __ldg(&yv[(size_t)s1 * 32 + lane]);
                float4 v2 = __ldg(&yv[(size_t)s2 * 32 + lane]);
                float4 v3 = __ldg(&yv[(size_t)s3 * 32 + lane]);
                a.x += (v0.x + v1.x) + (v2.x + v3.x);
                a.y += (v0.y + v1.y) + (v2.y + v3.y);
                a.z += (v0.z + v1.z) + (v2.z + v3.z);
                a.w += (v0.w + v1.w) + (v2.w + v3.w);
            }
            for (; i < cnt; i++) {
                int s0 = g_srcs[start + i];
                float4 v0 = __ldg(&yv[(size_t)s0 * 32 + lane]);
                a.x += v0.x; a.y += v0.y; a.z += v0.z; a.w += v0.w;
            }
            float inv = 1.0f / fmaxf((float)cnt, 1.0f);
            float4* orow = (float4*)(out + (size_t)node * DD);
            float4 yr = orow[lane];
            float ox = a.x * inv + yr.x;
            float oy = a.y * inv + yr.y;
            float oz = a.z * inv + yr.z;
            float ow = a.w * inv + yr.w;
            ox = (ox > 0.f) ? ox : expm1f(ox);
            oy = (oy > 0.f) ? oy : expm1f(oy);
            oz = (oz > 0.f) ? oz : expm1f(oz);
            ow = (ow > 0.f) ? ow : expm1f(ow);
            orow[lane] = make_float4(ox, oy, oz, ow);
        }
    }

    // ---- tail: edge_index passthrough ----
    if (do_tail) {
        for (int t = cta * NTHR + tid; t < 2 * NE; t += ncta * NTHR)
            out[NND + t] = (float)ld_idx(ei, t, is64);
    }

    // ---- depart: last CTA out resets all cross-launch state ----
    __syncthreads();
    if (tid == 0) {
        __threadfence();
        unsigned d = atomicAdd(&g_bar_dep, 1u);
        if (d == (unsigned)ncta - 1u) {
            g_bar_cnt = 0; g_bar_phase = 0; g_bar_dep = 0;
            g_sub_cnt = 0; g_sub_phase = 0;
            g_tile = 0;    g_total = 0;
        }
    }
}

// ---------------- launch ----------------
extern "C" void kernel_launch(void* const* d_in, const int* in_sizes, int n_in,
                              void* d_out, int out_size) {
    const float* x  = (const float*)d_in[0];
    const void*  ei = d_in[1];
    const float* Wl = (const float*)d_in[2];
    const float* bl = (const float*)d_in[3];
    const float* Wr = (const float*)d_in[4];
    float* out = (float*)d_out;

    int dev = 0;
    cudaGetDevice(&dev);
    int ncta = 0;
    cudaDeviceGetAttribute(&ncta, cudaDevAttrMultiProcessorCount, dev);
    if (ncta <= 0) ncta = 148;
    int csrn = ncta / 4;
    if (csrn < 1) csrn = 1;
    int do_tail = (out_size >= NND + 2 * NE) ? 1 : 0;

    cudaFuncSetAttribute(k_mega, cudaFuncAttributeMaxDynamicSharedMemorySize,
                         SMEM_BYTES);
    k_mega<<<ncta, NTHR, SMEM_BYTES>>>(x, ei, Wl, bl, Wr, out,
                                       ncta, csrn, do_tail);
}

// round 7
// speedup vs baseline: 1.4156x; 1.0738x over previous
#include <cuda_runtime.h>
#include <cuda_bf16.h>
#include <math.h>
#include <stdint.h>

#define NN 50000
#define NE 600000
#define DD 128
#define NND (NN * DD)
#define TROWS 128
#define NT ((NN + TROWS - 1) / TROWS)   // 391 tiles
#define NTHR 512
#define RSTR 272                         // smem row stride in bytes (17*16)

// ---- smem byte offsets ----
#define SM_BH   0                        // B-hi: 256 rows x 272B
#define SM_BL   69632                    // B-lo
#define SM_AH   139264                   // A-hi: 128 rows x 272B
#define SM_AL   174080                   // A-lo
#define SM_BIAS 208896                   // 128 floats
#define SM_T    209408
#define SMEM_BYTES 209424

// ---------------- device scratch ----------------
__device__ int   g_is64;
__device__ int   g_counts[NN];
__device__ int   g_offsets[NN];
__device__ int   g_cursor[NN];
__device__ int   g_srcs[NE];
__device__ float g_yl[(size_t)NN * DD];          // x @ Wl.T  (25.6 MB)
__device__ unsigned g_total   = 0;
__device__ unsigned g_tile    = 0;
__device__ unsigned g_bar_cnt = 0;
__device__ volatile unsigned g_bar_phase = 0;
__device__ unsigned g_bar_dep = 0;
__device__ unsigned g_sub_cnt = 0;
__device__ volatile unsigned g_sub_phase = 0;

// ---------------- helpers ----------------
__device__ __forceinline__ uint32_t s2u(const void* p) {
    uint32_t a;
    asm("{ .reg .u64 t; cvta.to.shared.u64 t, %1; cvt.u32.u64 %0, t; }"
        : "=r"(a) : "l"(p));
    return a;
}
__device__ __forceinline__ void ldsm4(uint32_t* r, uint32_t addr) {
    asm volatile("ldmatrix.sync.aligned.m8n8.x4.shared.b16 {%0,%1,%2,%3}, [%4];"
        : "=r"(r[0]), "=r"(r[1]), "=r"(r[2]), "=r"(r[3]) : "r"(addr));
}
__device__ __forceinline__ void mma_bf16(float* c, const uint32_t* a,
                                         const uint32_t* b) {
    asm volatile("mma.sync.aligned.m16n8k16.row.col.f32.bf16.bf16.f32 "
        "{%0,%1,%2,%3}, {%4,%5,%6,%7}, {%8,%9}, {%0,%1,%2,%3};"
        : "+f"(c[0]), "+f"(c[1]), "+f"(c[2]), "+f"(c[3])
        : "r"(a[0]), "r"(a[1]), "r"(a[2]), "r"(a[3]), "r"(b[0]), "r"(b[1]));
}
__device__ __forceinline__ int ld_idx(const void* ei, long long pos, int is64) {
    return is64 ? (int)((const long long*)ei)[pos] : ((const int*)ei)[pos];
}
__device__ __forceinline__ uint32_t packbf(float a, float b) {
    uint32_t r;
    asm("cvt.rn.satfinite.bf16x2.f32 %0, %1, %2;" : "=r"(r) : "f"(b), "f"(a));
    return r;
}
// split 2 consecutive f32 into packed bf16 hi pair + lo (residual) pair
__device__ __forceinline__ void split2(float f0, float f1, uint32_t& h, uint32_t& l) {
    __nv_bfloat16 h0 = __float2bfloat16_rn(f0);
    __nv_bfloat16 h1 = __float2bfloat16_rn(f1);
    float r0 = f0 - __bfloat162float(h0);
    float r1 = f1 - __bfloat162float(h1);
    h = ((uint32_t)__bfloat16_as_ushort(h1) << 16) | __bfloat16_as_ushort(h0);
    l = packbf(r0, r1);
}

__device__ __forceinline__ void grid_barrier(unsigned use, unsigned ncta) {
    __syncthreads();
    if (threadIdx.x == 0) {
        __threadfence();
        unsigned n = atomicAdd(&g_bar_cnt, 1u);
        if (n == use * ncta - 1u) g_bar_phase = use;
        else while (g_bar_phase < use) __nanosleep(64);
        __threadfence();
    }
    __syncthreads();
}
__device__ __forceinline__ void sub_barrier(unsigned use, unsigned csrn) {
    __syncthreads();
    if (threadIdx.x == 0) {
        __threadfence();
        unsigned n = atomicAdd(&g_sub_cnt, 1u);
        if (n == use * csrn - 1u) g_sub_phase = use;
        else while (g_sub_phase < use) __nanosleep(64);
        __threadfence();
    }
    __syncthreads();
}

// ---------------- the persistent mega-kernel ----------------
__global__ void __launch_bounds__(NTHR, 1)
k_mega(const float* __restrict__ x, const void* __restrict__ ei,
       const float* __restrict__ Wl, const float* __restrict__ bl,
       const float* __restrict__ Wr, float* __restrict__ out,
       int ncta, int csrn, int do_tail) {
    extern __shared__ char sm[];
    const uint32_t sb = s2u(sm);
    float* bias = (float*)(sm + SM_BIAS);
    volatile int* sm_t = (volatile int*)(sm + SM_T);

    const int tid  = threadIdx.x;
    const int cta  = blockIdx.x;
    const int wid  = tid >> 5;
    const int lane = tid & 31;

    // ---- init: dtype detect, zero counts ----
    if (cta == 0 && wid == 0) {
        const int* p = (const int*)ei;
        int v = p[lane * 2 + 1] | p[64 + lane * 2 + 1] |
                p[128 + lane * 2 + 1] | p[192 + lane * 2 + 1];
        unsigned any = __ballot_sync(0xffffffffu, v != 0);
        if (lane == 0) g_is64 = (any == 0u);
    }
    for (int i = cta * NTHR + tid; i < NN; i += ncta * NTHR) g_counts[i] = 0;

    // ---- stage B = [Wl;Wr] split hi/lo bf16, [n][k] k-contig, stride 272B ----
    {
        int n = tid & 255, kh = tid >> 8;      // kh: 0/1 -> k 0..63 / 64..127
        const float* wrow = ((n < 128) ? (Wl + (size_t)n * DD)
                                       : (Wr + (size_t)(n - 128) * DD)) + kh * 64;
        char* bh = sm + SM_BH + n * RSTR + kh * 128;
        char* blo = sm + SM_BL + n * RSTR + kh * 128;
        #pragma unroll
        for (int u = 0; u < 8; u++) {
            float4 v0 = *(const float4*)(wrow + u * 8);
            float4 v1 = *(const float4*)(wrow + u * 8 + 4);
            uint4 hh, ll;
            split2(v0.x, v0.y, hh.x, ll.x);
            split2(v0.z, v0.w, hh.y, ll.y);
            split2(v1.x, v1.y, hh.z, ll.z);
            split2(v1.z, v1.w, hh.w, ll.w);
            *(uint4*)(bh + u * 16) = hh;
            *(uint4*)(blo + u * 16) = ll;
        }
    }
    if (tid < 128) bias[tid] = bl[tid];

    grid_barrier(1, ncta);
    const int is64 = g_is64;

    // ---- CSR build on csrn CTAs ----
    if (cta < csrn) {
        const int step = csrn * NTHR;
        const int tg = cta * NTHR + tid;
        for (int e = tg; e < NE; e += step)
            atomicAdd(&g_counts[ld_idx(ei, (long long)NE + e, is64)], 1);
        sub_barrier(1, (unsigned)csrn);
        for (int wb = cta * NTHR + wid * 32; wb < NN; wb += step) {
            int i = wb + lane;
            int c = (i < NN) ? g_counts[i] : 0;
            int s = c;
            #pragma unroll
            for (int off = 1; off < 32; off <<= 1) {
                int v = __shfl_up_sync(0xffffffffu, s, off);
                if (lane >= off) s += v;
            }
            int tot = __shfl_sync(0xffffffffu, s, 31);
            unsigned base = 0;
            if (lane == 31) base = atomicAdd(&g_total, (unsigned)tot);
            base = __shfl_sync(0xffffffffu, base, 31);
            int excl = (int)base + s - c;
            if (i < NN) { g_offsets[i] = excl; g_cursor[i] = excl; }
        }
        sub_barrier(2, (unsigned)csrn);
        for (int e = tg; e < NE; e += step) {
            int src = ld_idx(ei, e, is64);
            int dst = ld_idx(ei, (long long)NE + e, is64);
            int p = atomicAdd(&g_cursor[dst], 1);
            g_srcs[p] = src;
        }
    } else if (do_tail) {
        // ---- tail overlapped with CSR: edge_index passthrough ----
        const int nt2 = ncta - csrn;
        for (int t = (cta - csrn) * NTHR + tid; t < 2 * NE; t += nt2 * NTHR)
            out[NND + t] = (float)ld_idx(ei, t, is64);
    }

    // ---- GEMM: D[128,256] = x_tile @ [Wl;Wr]^T via mma.sync bf16 3-split ----
    // warp tile m32 x n64: mw = (wid&3)*32, nw = (wid>>2)*64
    {
        const int mw = (wid & 3) * 32;
        const int nw = (wid >> 2) * 64;
        const int g = lane >> 3, r = lane & 7;
        const uint32_t aoff = (uint32_t)((mw + r + (g & 1) * 8) * RSTR + (g >> 1) * 16);
        const uint32_t boff = (uint32_t)((nw + r + (g >> 1) * 8) * RSTR + (g & 1) * 16);
        const int tr = lane >> 2;            // 0..7
        const int tc = (lane & 3) * 2;

        for (;;) {
            __syncthreads();
            if (tid == 0) *sm_t = (int)atomicAdd(&g_tile, 1u);
            __syncthreads();
            int t = *sm_t;
            if (t >= NT) break;
            int row0 = t * TROWS;

            // stage A tile: m = tid&127, k-quarter = tid>>7 (32 k values)
            {
                int m = tid & 127, seg = tid >> 7;
                int gr = row0 + m;
                const float* xrow = x + (size_t)gr * DD + seg * 32;
                char* ah = sm + SM_AH + m * RSTR + seg * 64;
                char* al = sm + SM_AL + m * RSTR + seg * 64;
                #pragma unroll
                for (int u = 0; u < 4; u++) {
                    float4 v0, v1;
                    if (gr < NN) {
                        v0 = *(const float4*)(xrow + u * 8);
                        v1 = *(const float4*)(xrow + u * 8 + 4);
                    } else {
                        v0 = make_float4(0.f, 0.f, 0.f, 0.f); v1 = v0;
                    }
                    uint4 hh, ll;
                    split2(v0.x, v0.y, hh.x, ll.x);
                    split2(v0.z, v0.w, hh.y, ll.y);
                    split2(v1.x, v1.y, hh.z, ll.z);
                    split2(v1.z, v1.w, hh.w, ll.w);
                    *(uint4*)(ah + u * 16) = hh;
                    *(uint4*)(al + u * 16) = ll;
                }
            }
            __syncthreads();

            float acc[2][8][4];
            #pragma unroll
            for (int mi = 0; mi < 2; mi++)
                #pragma unroll
                for (int ni = 0; ni < 8; ni++)
                    #pragma unroll
                    for (int q = 0; q < 4; q++) acc[mi][ni][q] = 0.f;

            #pragma unroll 1
            for (int s = 0; s < 3; s++) {
                // s=0: Ah*Bh, s=1: Ah*Bl, s=2: Al*Bh
                uint32_t abase = sb + (s == 2 ? SM_AL : SM_AH) + aoff;
                uint32_t bbase = sb + (s == 1 ? SM_BL : SM_BH) + boff;
                #pragma unroll
                for (int k = 0; k < 8; k++) {
                    uint32_t a[2][4], b[4][4];
                    ldsm4(a[0], abase + k * 32);
                    ldsm4(a[1], abase + 16 * RSTR + k * 32);
                    #pragma unroll
                    for (int bg = 0; bg < 4; bg++)
                        ldsm4(b[bg], bbase + bg * 16 * RSTR + k * 32);
                    #pragma unroll
                    for (int mi = 0; mi < 2; mi++)
                        #pragma unroll
                        for (int ni = 0; ni < 8; ni++)
                            mma_bf16(acc[mi][ni], a[mi], &b[ni >> 1][(ni & 1) * 2]);
                }
            }

            // epilogue: nw<128 -> g_yl ; nw>=128 -> out + bias
            #pragma unroll
            for (int mi = 0; mi < 2; mi++) {
                #pragma unroll
                for (int rr = 0; rr < 2; rr++) {
                    int row = row0 + mw + mi * 16 + tr + rr * 8;
                    if (row < NN) {
                        if (nw < 128) {
                            float* dst = g_yl + (size_t)row * DD + nw + tc;
                            #pragma unroll
                            for (int ni = 0; ni < 8; ni++) {
                                float2 v = make_float2(acc[mi][ni][rr * 2],
                                                       acc[mi][ni][rr * 2 + 1]);
                                *(float2*)(dst + ni * 8) = v;
                            }
                        } else {
                            int j0 = nw - 128 + tc;
                            float* dst = out + (size_t)row * DD + j0;
                            #pragma unroll
                            for (int ni = 0; ni < 8; ni++) {
                                float2 v = make_float2(
                                    acc[mi][ni][rr * 2]     + bias[j0 + ni * 8],
                                    acc[mi][ni][rr * 2 + 1] + bias[j0 + ni * 8 + 1]);
                                *(float2*)(dst + ni * 8) = v;
                            }
                        }
                    }
                }
            }
        }
    }

    grid_barrier(2, ncta);

    // ---- aggregate: out = ELU(mean(y_l[src]) + y_r), warp per node ----
    // lane-parallel src prefetch: one coalesced LDG.32 fetches 32 indices,
    // then the gather loop runs dependency-free off shuffles (MLP ~= degree).
    {
        const int warps = ncta * 16;
        const float4* yv = (const float4*)g_yl;
        for (int node = cta * 16 + wid; node < NN; node += warps) {
            int start = g_offsets[node];
            int cnt   = g_counts[node];
            float4* orow = (float4*)(out + (size_t)node * DD);
            float4 yr = orow[lane];                 // prefetch out row
            int msrc = 0;
            if (lane < cnt) msrc = g_srcs[start + lane];
            float4 a0 = make_float4(0.f, 0.f, 0.f, 0.f);
            float4 a1 = make_float4(0.f, 0.f, 0.f, 0.f);
            int nb = cnt < 32 ? cnt : 32;
            int j = 0;
            for (; j + 3 < nb; j += 4) {
                int s0 = __shfl_sync(0xffffffffu, msrc, j);
                int s1 = __shfl_sync(0xffffffffu, msrc, j + 1);
                int s2 = __shfl_sync(0xffffffffu, msrc, j + 2);
                int s3 = __shfl_sync(0xffffffffu, msrc, j + 3);
                float4 v0 = __ldg(&yv[(size_t)s0 * 32 + lane]);
                float4 v1 = __ldg(&yv[(size_t)s1 * 32 + lane]);
                float4 v2 = __ldg(&yv[(size_t)s2 * 32 + lane]);
                float4 v3 = __ldg(&yv[(size_t)s3 * 32 + lane]);
                a0.x += v0.x + v1.x; a0.y += v0.y + v1.y;
                a0.z += v0.z + v1.z; a0.w += v0.w + v1.w;
                a1.x += v2.x + v3.x; a1.y += v2.y + v3.y;
                a1.z += v2.z + v3.z; a1.w += v2.w + v3.w;
            }
            for (; j < nb; j++) {
                int s0 = __shfl_sync(0xffffffffu, msrc, j);
                float4 v0 = __ldg(&yv[(size_t)s0 * 32 + lane]);
                a0.x += v0.x; a0.y += v0.y; a0.z += v0.z; a0.w += v0.w;
            }
            for (int i = 32; i < cnt; i++) {        // rare overflow (deg > 32)
                int s0 = g_srcs[start + i];
                float4 v0 = __ldg(&yv[(size_t)s0 * 32 + lane]);
                a0.x += v0.x; a0.y += v0.y; a0.z += v0.z; a0.w += v0.w;
            }
            float inv = 1.0f / fmaxf((float)cnt, 1.0f);
            float ox = (a0.x + a1.x) * inv + yr.x;
            float oy = (a0.y + a1.y) * inv + yr.y;
            float oz = (a0.z + a1.z) * inv + yr.z;
            float ow = (a0.w + a1.w) * inv + yr.w;
            ox = (ox > 0.f) ? ox : expm1f(ox);
            oy = (oy > 0.f) ? oy : expm1f(oy);
            oz = (oz > 0.f) ? oz : expm1f(oz);
            ow = (ow > 0.f) ? ow : expm1f(ow);
            orow[lane] = make_float4(ox, oy, oz, ow);
        }
    }

    // ---- depart: last CTA out resets all cross-launch state ----
    __syncthreads();
    if (tid == 0) {
        __threadfence();
        unsigned d = atomicAdd(&g_bar_dep, 1u);
        if (d == (unsigned)ncta - 1u) {
            g_bar_cnt = 0; g_bar_phase = 0; g_bar_dep = 0;
            g_sub_cnt = 0; g_sub_phase = 0;
            g_tile = 0;    g_total = 0;
        }
    }
}

// ---------------- launch ----------------
extern "C" void kernel_launch(void* const* d_in, const int* in_sizes, int n_in,
                              void* d_out, int out_size) {
    const float* x  = (const float*)d_in[0];
    const void*  ei = d_in[1];
    const float* Wl = (const float*)d_in[2];
    const float* bl = (const float*)d_in[3];
    const float* Wr = (const float*)d_in[4];
    float* out = (float*)d_out;

    int dev = 0;
    cudaGetDevice(&dev);
    int ncta = 0;
    cudaDeviceGetAttribute(&ncta, cudaDevAttrMultiProcessorCount, dev);
    if (ncta <= 0) ncta = 148;
    int csrn = ncta / 4;
    if (csrn < 1) csrn = 1;
    int do_tail = (out_size >= NND + 2 * NE) ? 1 : 0;

    cudaFuncSetAttribute(k_mega, cudaFuncAttributeMaxDynamicSharedMemorySize,
                         SMEM_BYTES);
    k_mega<<<ncta, NTHR, SMEM_BYTES>>>(x, ei, Wl, bl, Wr, out,
                                       ncta, csrn, do_tail);
}

// round 8
// speedup vs baseline: 1.4224x; 1.0048x over previous
#include <cuda_runtime.h>
#include <cuda_bf16.h>
#include <cuda_fp16.h>
#include <math.h>
#include <stdint.h>

#define NN 50000
#define NE 600000
#define DD 128
#define NND (NN * DD)
#define TROWS 128
#define NT ((NN + TROWS - 1) / TROWS)   // 391 tiles
#define NTHR 512
#define RSTR 272                         // smem row stride in bytes (17*16)

// ---- smem byte offsets ----
#define SM_BH   0                        // B-hi: 256 rows x 272B
#define SM_BL   69632                    // B-lo
#define SM_AH   139264                   // A-hi: 128 rows x 272B
#define SM_AL   174080                   // A-lo
#define SM_BIAS 208896                   // 128 floats
#define SM_T    209408
#define SMEM_BYTES 209424

// ---------------- device scratch ----------------
__device__ int   g_is64;
__device__ int   g_counts[NN];
__device__ int   g_offsets[NN];
__device__ int   g_cursor[NN];
__device__ int   g_srcs[NE];
__device__ __half g_ylh[(size_t)NN * DD];        // x @ Wl.T in fp16 (12.8 MB)
__device__ unsigned g_total   = 0;
__device__ unsigned g_tile    = 0;
__device__ unsigned g_bar_cnt = 0;
__device__ volatile unsigned g_bar_phase = 0;
__device__ unsigned g_bar_dep = 0;
__device__ unsigned g_sub_cnt = 0;
__device__ volatile unsigned g_sub_phase = 0;

// ---------------- helpers ----------------
__device__ __forceinline__ uint32_t s2u(const void* p) {
    uint32_t a;
    asm("{ .reg .u64 t; cvta.to.shared.u64 t, %1; cvt.u32.u64 %0, t; }"
        : "=r"(a) : "l"(p));
    return a;
}
__device__ __forceinline__ void ldsm4(uint32_t* r, uint32_t addr) {
    asm volatile("ldmatrix.sync.aligned.m8n8.x4.shared.b16 {%0,%1,%2,%3}, [%4];"
        : "=r"(r[0]), "=r"(r[1]), "=r"(r[2]), "=r"(r[3]) : "r"(addr));
}
__device__ __forceinline__ void mma_f16(float* c, const uint32_t* a,
                                        const uint32_t* b) {
    asm volatile("mma.sync.aligned.m16n8k16.row.col.f32.f16.f16.f32 "
        "{%0,%1,%2,%3}, {%4,%5,%6,%7}, {%8,%9}, {%0,%1,%2,%3};"
        : "+f"(c[0]), "+f"(c[1]), "+f"(c[2]), "+f"(c[3])
        : "r"(a[0]), "r"(a[1]), "r"(a[2]), "r"(a[3]), "r"(b[0]), "r"(b[1]));
}
__device__ __forceinline__ int ld_idx(const void* ei, long long pos, int is64) {
    return is64 ? (int)((const long long*)ei)[pos] : ((const int*)ei)[pos];
}
// split 2 consecutive f32 into packed fp16 hi pair + fp16 residual pair
__device__ __forceinline__ void split2h(float f0, float f1, uint32_t& h, uint32_t& l) {
    __half h0 = __float2half_rn(f0);
    __half h1 = __float2half_rn(f1);
    float r0 = f0 - __half2float(h0);
    float r1 = f1 - __half2float(h1);
    __half l0 = __float2half_rn(r0);
    __half l1 = __float2half_rn(r1);
    h = ((uint32_t)__half_as_ushort(h1) << 16) | __half_as_ushort(h0);
    l = ((uint32_t)__half_as_ushort(l1) << 16) | __half_as_ushort(l0);
}

__device__ __forceinline__ void grid_barrier(unsigned use, unsigned ncta) {
    __syncthreads();
    if (threadIdx.x == 0) {
        __threadfence();
        unsigned n = atomicAdd(&g_bar_cnt, 1u);
        if (n == use * ncta - 1u) g_bar_phase = use;
        else while (g_bar_phase < use) __nanosleep(64);
        __threadfence();
    }
    __syncthreads();
}
__device__ __forceinline__ void sub_barrier(unsigned use, unsigned csrn) {
    __syncthreads();
    if (threadIdx.x == 0) {
        __threadfence();
        unsigned n = atomicAdd(&g_sub_cnt, 1u);
        if (n == use * csrn - 1u) g_sub_phase = use;
        else while (g_sub_phase < use) __nanosleep(64);
        __threadfence();
    }
    __syncthreads();
}

// ---------------- the persistent mega-kernel ----------------
__global__ void __launch_bounds__(NTHR, 1)
k_mega(const float* __restrict__ x, const void* __restrict__ ei,
       const float* __restrict__ Wl, const float* __restrict__ bl,
       const float* __restrict__ Wr, float* __restrict__ out,
       int ncta, int csrn, int do_tail) {
    extern __shared__ char sm[];
    const uint32_t sb = s2u(sm);
    float* bias = (float*)(sm + SM_BIAS);
    volatile int* sm_t = (volatile int*)(sm + SM_T);

    const int tid  = threadIdx.x;
    const int cta  = blockIdx.x;
    const int wid  = tid >> 5;
    const int lane = tid & 31;

    // ---- init: dtype detect, zero counts ----
    if (cta == 0 && wid == 0) {
        const int* p = (const int*)ei;
        int v = p[lane * 2 + 1] | p[64 + lane * 2 + 1] |
                p[128 + lane * 2 + 1] | p[192 + lane * 2 + 1];
        unsigned any = __ballot_sync(0xffffffffu, v != 0);
        if (lane == 0) g_is64 = (any == 0u);
    }
    for (int i = cta * NTHR + tid; i < NN; i += ncta * NTHR) g_counts[i] = 0;

    // ---- stage B = [Wl;Wr] split hi/lo fp16, [n][k] k-contig, stride 272B ----
    {
        int n = tid & 255, kh = tid >> 8;      // kh: 0/1 -> k 0..63 / 64..127
        const float* wrow = ((n < 128) ? (Wl + (size_t)n * DD)
                                       : (Wr + (size_t)(n - 128) * DD)) + kh * 64;
        char* bh = sm + SM_BH + n * RSTR + kh * 128;
        char* blo = sm + SM_BL + n * RSTR + kh * 128;
        #pragma unroll
        for (int u = 0; u < 8; u++) {
            float4 v0 = *(const float4*)(wrow + u * 8);
            float4 v1 = *(const float4*)(wrow + u * 8 + 4);
            uint4 hh, ll;
            split2h(v0.x, v0.y, hh.x, ll.x);
            split2h(v0.z, v0.w, hh.y, ll.y);
            split2h(v1.x, v1.y, hh.z, ll.z);
            split2h(v1.z, v1.w, hh.w, ll.w);
            *(uint4*)(bh + u * 16) = hh;
            *(uint4*)(blo + u * 16) = ll;
        }
    }
    if (tid < 128) bias[tid] = bl[tid];

    grid_barrier(1, ncta);
    const int is64 = g_is64;

    // ---- CSR build on csrn CTAs ----
    if (cta < csrn) {
        const int step = csrn * NTHR;
        const int tg = cta * NTHR + tid;
        for (int e = tg; e < NE; e += step)
            atomicAdd(&g_counts[ld_idx(ei, (long long)NE + e, is64)], 1);
        sub_barrier(1, (unsigned)csrn);
        for (int wb = cta * NTHR + wid * 32; wb < NN; wb += step) {
            int i = wb + lane;
            int c = (i < NN) ? g_counts[i] : 0;
            int s = c;
            #pragma unroll
            for (int off = 1; off < 32; off <<= 1) {
                int v = __shfl_up_sync(0xffffffffu, s, off);
                if (lane >= off) s += v;
            }
            int tot = __shfl_sync(0xffffffffu, s, 31);
            unsigned base = 0;
            if (lane == 31) base = atomicAdd(&g_total, (unsigned)tot);
            base = __shfl_sync(0xffffffffu, base, 31);
            int excl = (int)base + s - c;
            if (i < NN) { g_offsets[i] = excl; g_cursor[i] = excl; }
        }
        sub_barrier(2, (unsigned)csrn);
        for (int e = tg; e < NE; e += step) {
            int src = ld_idx(ei, e, is64);
            int dst = ld_idx(ei, (long long)NE + e, is64);
            int p = atomicAdd(&g_cursor[dst], 1);
            g_srcs[p] = src;
        }
    } else if (do_tail) {
        // ---- tail overlapped with CSR: edge_index passthrough ----
        const int nt2 = ncta - csrn;
        for (int t = (cta - csrn) * NTHR + tid; t < 2 * NE; t += nt2 * NTHR)
            out[NND + t] = (float)ld_idx(ei, t, is64);
    }

    // ---- GEMM: D[128,256] = x_tile @ [Wl;Wr]^T via mma.sync fp16 split ----
    // warp tile m32 x n64. y_l warps (nw<128): 2 split terms (feeds mean, fp16
    // store anyway); y_r warps: 3 terms.
    {
        const int mw = (wid & 3) * 32;
        const int nw = (wid >> 2) * 64;
        const int nsp = (nw < 128) ? 2 : 3;
        const int g = lane >> 3, r = lane & 7;
        const uint32_t aoff = (uint32_t)((mw + r + (g & 1) * 8) * RSTR + (g >> 1) * 16);
        const uint32_t boff = (uint32_t)((nw + r + (g >> 1) * 8) * RSTR + (g & 1) * 16);
        const int tr = lane >> 2;            // 0..7
        const int tc = (lane & 3) * 2;

        for (;;) {
            __syncthreads();
            if (tid == 0) *sm_t = (int)atomicAdd(&g_tile, 1u);
            __syncthreads();
            int t = *sm_t;
            if (t >= NT) break;
            int row0 = t * TROWS;

            // stage A tile: m = tid&127, k-quarter = tid>>7 (32 k values)
            {
                int m = tid & 127, seg = tid >> 7;
                int gr = row0 + m;
                const float* xrow = x + (size_t)gr * DD + seg * 32;
                char* ah = sm + SM_AH + m * RSTR + seg * 64;
                char* al = sm + SM_AL + m * RSTR + seg * 64;
                #pragma unroll
                for (int u = 0; u < 4; u++) {
                    float4 v0, v1;
                    if (gr < NN) {
                        v0 = *(const float4*)(xrow + u * 8);
                        v1 = *(const float4*)(xrow + u * 8 + 4);
                    } else {
                        v0 = make_float4(0.f, 0.f, 0.f, 0.f); v1 = v0;
                    }
                    uint4 hh, ll;
                    split2h(v0.x, v0.y, hh.x, ll.x);
                    split2h(v0.z, v0.w, hh.y, ll.y);
                    split2h(v1.x, v1.y, hh.z, ll.z);
                    split2h(v1.z, v1.w, hh.w, ll.w);
                    *(uint4*)(ah + u * 16) = hh;
                    *(uint4*)(al + u * 16) = ll;
                }
            }
            __syncthreads();

            float acc[2][8][4];
            #pragma unroll
            for (int mi = 0; mi < 2; mi++)
                #pragma unroll
                for (int ni = 0; ni < 8; ni++)
                    #pragma unroll
                    for (int q = 0; q < 4; q++) acc[mi][ni][q] = 0.f;

            #pragma unroll 1
            for (int s = 0; s < nsp; s++) {
                // s=0: Ah*Bh, s=1: Ah*Bl, s=2: Al*Bh
                uint32_t abase = sb + (s == 2 ? SM_AL : SM_AH) + aoff;
                uint32_t bbase = sb + (s == 1 ? SM_BL : SM_BH) + boff;
                #pragma unroll
                for (int k = 0; k < 8; k++) {
                    uint32_t a[2][4], b[4][4];
                    ldsm4(a[0], abase + k * 32);
                    ldsm4(a[1], abase + 16 * RSTR + k * 32);
                    #pragma unroll
                    for (int bg = 0; bg < 4; bg++)
                        ldsm4(b[bg], bbase + bg * 16 * RSTR + k * 32);
                    #pragma unroll
                    for (int mi = 0; mi < 2; mi++)
                        #pragma unroll
                        for (int ni = 0; ni < 8; ni++)
                            mma_f16(acc[mi][ni], a[mi], &b[ni >> 1][(ni & 1) * 2]);
                }
            }

            // epilogue: nw<128 -> g_ylh (fp16) ; nw>=128 -> out + bias (f32)
            #pragma unroll
            for (int mi = 0; mi < 2; mi++) {
                #pragma unroll
                for (int rr = 0; rr < 2; rr++) {
                    int row = row0 + mw + mi * 16 + tr + rr * 8;
                    if (row < NN) {
                        if (nw < 128) {
                            __half* dst = g_ylh + (size_t)row * DD + nw + tc;
                            #pragma unroll
                            for (int ni = 0; ni < 8; ni++) {
                                __half2 hv = __floats2half2_rn(
                                    acc[mi][ni][rr * 2], acc[mi][ni][rr * 2 + 1]);
                                *(__half2*)(dst + ni * 8) = hv;
                            }
                        } else {
                            int j0 = nw - 128 + tc;
                            float* dst = out + (size_t)row * DD + j0;
                            #pragma unroll
                            for (int ni = 0; ni < 8; ni++) {
                                float2 v = make_float2(
                                    acc[mi][ni][rr * 2]     + bias[j0 + ni * 8],
                                    acc[mi][ni][rr * 2 + 1] + bias[j0 + ni * 8 + 1]);
                                *(float2*)(dst + ni * 8) = v;
                            }
                        }
                    }
                }
            }
        }
    }

    grid_barrier(2, ncta);

    // ---- aggregate: out = ELU(mean(y_l[src]) + y_r), warp per node ----
    // fp16 y_l rows: 8B (4 halfs) per lane per gather; srcs prefetched
    // lane-parallel, gather loop driven by shuffles (dependency-free).
    {
        const int warps = ncta * 16;
        const uint2* yv = (const uint2*)g_ylh;   // row stride = 32 uint2
        for (int node = cta * 16 + wid; node < NN; node += warps) {
            int start = g_offsets[node];
            int cnt   = g_counts[node];
            float4* orow = (float4*)(out + (size_t)node * DD);
            float4 yr = orow[lane];                 // prefetch out row
            int msrc = 0;
            if (lane < cnt) msrc = g_srcs[start + lane];
            float4 a0 = make_float4(0.f, 0.f, 0.f, 0.f);
            float4 a1 = make_float4(0.f, 0.f, 0.f, 0.f);
            int nb = cnt < 32 ? cnt : 32;
            int j = 0;
            for (; j + 3 < nb; j += 4) {
                int s0 = __shfl_sync(0xffffffffu, msrc, j);
                int s1 = __shfl_sync(0xffffffffu, msrc, j + 1);
                int s2 = __shfl_sync(0xffffffffu, msrc, j + 2);
                int s3 = __shfl_sync(0xffffffffu, msrc, j + 3);
                uint2 u0 = __ldg(&yv[(size_t)s0 * 32 + lane]);
                uint2 u1 = __ldg(&yv[(size_t)s1 * 32 + lane]);
                uint2 u2 = __ldg(&yv[(size_t)s2 * 32 + lane]);
                uint2 u3 = __ldg(&yv[(size_t)s3 * 32 + lane]);
                float2 p0 = __half22float2(*(__half2*)&u0.x);
                float2 q0 = __half22float2(*(__half2*)&u0.y);
                float2 p1 = __half22float2(*(__half2*)&u1.x);
                float2 q1 = __half22float2(*(__half2*)&u1.y);
                float2 p2 = __half22float2(*(__half2*)&u2.x);
                float2 q2 = __half22float2(*(__half2*)&u2.y);
                float2 p3 = __half22float2(*(__half2*)&u3.x);
                float2 q3 = __half22float2(*(__half2*)&u3.y);
                a0.x += p0.x + p1.x; a0.y += p0.y + p1.y;
                a0.z += q0.x + q1.x; a0.w += q0.y + q1.y;
                a1.x += p2.x + p3.x; a1.y += p2.y + p3.y;
                a1.z += q2.x + q3.x; a1.w += q2.y + q3.y;
            }
            for (; j < nb; j++) {
                int s0 = __shfl_sync(0xffffffffu, msrc, j);
                uint2 u0 = __ldg(&yv[(size_t)s0 * 32 + lane]);
                float2 p0 = __half22float2(*(__half2*)&u0.x);
                float2 q0 = __half22float2(*(__half2*)&u0.y);
                a0.x += p0.x; a0.y += p0.y; a0.z += q0.x; a0.w += q0.y;
            }
            for (int i = 32; i < cnt; i++) {        // rare overflow (deg > 32)
                int s0 = g_srcs[start + i];
                uint2 u0 = __ldg(&yv[(size_t)s0 * 32 + lane]);
                float2 p0 = __half22float2(*(__half2*)&u0.x);
                float2 q0 = __half22float2(*(__half2*)&u0.y);
                a0.x += p0.x; a0.y += p0.y; a0.z += q0.x; a0.w += q0.y;
            }
            float inv = 1.0f / fmaxf((float)cnt, 1.0f);
            float ox = (a0.x + a1.x) * inv + yr.x;
            float oy = (a0.y + a1.y) * inv + yr.y;
            float oz = (a0.z + a1.z) * inv + yr.z;
            float ow = (a0.w + a1.w) * inv + yr.w;
            ox = (ox > 0.f) ? ox : expm1f(ox);
            oy = (oy > 0.f) ? oy : expm1f(oy);
            oz = (oz > 0.f) ? oz : expm1f(oz);
            ow = (ow > 0.f) ? ow : expm1f(ow);
            orow[lane] = make_float4(ox, oy, oz, ow);
        }
    }

    // ---- depart: last CTA out resets all cross-launch state ----
    __syncthreads();
    if (tid == 0) {
        __threadfence();
        unsigned d = atomicAdd(&g_bar_dep, 1u);
        if (d == (unsigned)ncta - 1u) {
            g_bar_cnt = 0; g_bar_phase = 0; g_bar_dep = 0;
            g_sub_cnt = 0; g_sub_phase = 0;
            g_tile = 0;    g_total = 0;
        }
    }
}

// ---------------- launch ----------------
extern "C" void kernel_launch(void* const* d_in, const int* in_sizes, int n_in,
                              void* d_out, int out_size) {
    const float* x  = (const float*)d_in[0];
    const void*  ei = d_in[1];
    const float* Wl = (const float*)d_in[2];
    const float* bl = (const float*)d_in[3];
    const float* Wr = (const float*)d_in[4];
    float* out = (float*)d_out;

    int dev = 0;
    cudaGetDevice(&dev);
    int ncta = 0;
    cudaDeviceGetAttribute(&ncta, cudaDevAttrMultiProcessorCount, dev);
    if (ncta <= 0) ncta = 148;
    int csrn = ncta / 4;
    if (csrn < 1) csrn = 1;
    int do_tail = (out_size >= NND + 2 * NE) ? 1 : 0;

    cudaFuncSetAttribute(k_mega, cudaFuncAttributeMaxDynamicSharedMemorySize,
                         SMEM_BYTES);
    k_mega<<<ncta, NTHR, SMEM_BYTES>>>(x, ei, Wl, bl, Wr, out,
                                       ncta, csrn, do_tail);
}

// round 11
// speedup vs baseline: 1.6834x; 1.1835x over previous
#include <cuda_runtime.h>
#include <cuda_fp16.h>
#include <math.h>
#include <stdint.h>

#define NN 50000
#define NE 600000
#define DD 128
#define NND (NN * DD)
#define TROWS 128
#define NT ((NN + TROWS - 1) / TROWS)   // 391 tiles
#define NTHR 512
#define RSTR 272                         // smem row stride in bytes (17*16)

// ---- smem byte offsets ----
#define SM_BH   0                        // B-hi: 256 rows x 272B
#define SM_BL   69632                    // B-lo
#define SM_A0   139264                   // A buf 0: 128 rows x 272B
#define SM_A1   174080                   // A buf 1
#define SM_BIAS 208896                   // 128 floats
#define SM_T    209408
#define SMEM_BYTES 209424

// ---------------- device scratch ----------------
__device__ int   g_is64;
__device__ int   g_counts[NN];
__device__ int   g_offsets[NN];
__device__ int   g_cursor[NN];
__device__ int   g_srcs[NE];
__device__ __align__(16) __half g_xh[(size_t)(NN + TROWS) * DD]; // fp16(x), padded
__device__ __align__(16) __half g_ylh[(size_t)NN * DD];          // x @ Wl.T fp16
__device__ unsigned g_total   = 0;
__device__ unsigned g_tile    = 0;
__device__ unsigned g_bar_cnt = 0;
__device__ volatile unsigned g_bar_phase = 0;
__device__ unsigned g_bar_dep = 0;
__device__ unsigned g_sub_cnt = 0;
__device__ volatile unsigned g_sub_phase = 0;

// ---------------- helpers ----------------
__device__ __forceinline__ uint32_t s2u(const void* p) {
    uint32_t a;
    asm("{ .reg .u64 t; cvta.to.shared.u64 t, %1; cvt.u32.u64 %0, t; }"
        : "=r"(a) : "l"(p));
    return a;
}
__device__ __forceinline__ void ldsm4(uint32_t* r, uint32_t addr) {
    asm volatile("ldmatrix.sync.aligned.m8n8.x4.shared.b16 {%0,%1,%2,%3}, [%4];"
        : "=r"(r[0]), "=r"(r[1]), "=r"(r[2]), "=r"(r[3]) : "r"(addr));
}
__device__ __forceinline__ void mma_f16(float* c, const uint32_t* a,
                                        const uint32_t* b) {
    asm volatile("mma.sync.aligned.m16n8k16.row.col.f32.f16.f16.f32 "
        "{%0,%1,%2,%3}, {%4,%5,%6,%7}, {%8,%9}, {%0,%1,%2,%3};"
        : "+f"(c[0]), "+f"(c[1]), "+f"(c[2]), "+f"(c[3])
        : "r"(a[0]), "r"(a[1]), "r"(a[2]), "r"(a[3]), "r"(b[0]), "r"(b[1]));
}
#define CP_ASYNC16(dst, src) \
    asm volatile("cp.async.cg.shared.global [%0], [%1], 16;" \
                 :: "r"(dst), "l"(src))
#define CP_COMMIT() asm volatile("cp.async.commit_group;" ::: "memory")
#define CP_WAIT0()  asm volatile("cp.async.wait_group 0;"  ::: "memory")

__device__ __forceinline__ int ld_idx(const void* ei, long long pos, int is64) {
    return is64 ? (int)((const long long*)ei)[pos] : ((const int*)ei)[pos];
}
// split 2 consecutive f32 into packed fp16 hi pair + fp16 residual pair
__device__ __forceinline__ void split2h(float f0, float f1, uint32_t& h, uint32_t& l) {
    __half h0 = __float2half_rn(f0);
    __half h1 = __float2half_rn(f1);
    float r0 = f0 - __half2float(h0);
    float r1 = f1 - __half2float(h1);
    __half l0 = __float2half_rn(r0);
    __half l1 = __float2half_rn(r1);
    h = ((uint32_t)__half_as_ushort(h1) << 16) | __half_as_ushort(h0);
    l = ((uint32_t)__half_as_ushort(l1) << 16) | __half_as_ushort(l0);
}

__device__ __forceinline__ void grid_barrier(unsigned use, unsigned ncta) {
    __syncthreads();
    if (threadIdx.x == 0) {
        __threadfence();
        unsigned n = atomicAdd(&g_bar_cnt, 1u);
        if (n == use * ncta - 1u) g_bar_phase = use;
        else while (g_bar_phase < use) __nanosleep(64);
        __threadfence();
    }
    __syncthreads();
}
__device__ __forceinline__ void sub_barrier(unsigned use, unsigned csrn) {
    __syncthreads();
    if (threadIdx.x == 0) {
        __threadfence();
        unsigned n = atomicAdd(&g_sub_cnt, 1u);
        if (n == use * csrn - 1u) g_sub_phase = use;
        else while (g_sub_phase < use) __nanosleep(64);
        __threadfence();
    }
    __syncthreads();
}

// stage one 128-row A tile (fp16, pre-converted) into smem via cp.async
__device__ __forceinline__ void stage_a(uint32_t sb, int row0, int which, int tid) {
    uint32_t ab = sb + (which ? SM_A1 : SM_A0);
    #pragma unroll
    for (int q = 0; q < 4; q++) {
        int c = tid + q * NTHR;          // 0..2047
        int m = c >> 4, ch = c & 15;
        uint32_t dst = ab + m * RSTR + ch * 16;
        const char* src = (const char*)(g_xh + (size_t)(row0 + m) * DD) + ch * 16;
        CP_ASYNC16(dst, src);
    }
}

// ---------------- the persistent mega-kernel ----------------
__global__ void __launch_bounds__(NTHR, 1)
k_mega(const float* __restrict__ x, const void* __restrict__ ei,
       const float* __restrict__ Wl, const float* __restrict__ bl,
       const float* __restrict__ Wr, float* __restrict__ out,
       int ncta, int csrn, int do_tail) {
    extern __shared__ char sm[];
    const uint32_t sb = s2u(sm);
    float* bias = (float*)(sm + SM_BIAS);
    volatile int* sm_t = (volatile int*)(sm + SM_T);

    const int tid  = threadIdx.x;
    const int cta  = blockIdx.x;
    const int wid  = tid >> 5;
    const int lane = tid & 31;

    // ---- init: dtype detect, zero counts, x -> fp16 ----
    if (cta == 0 && wid == 0) {
        const int* p = (const int*)ei;
        int v = p[lane * 2 + 1] | p[64 + lane * 2 + 1] |
                p[128 + lane * 2 + 1] | p[192 + lane * 2 + 1];
        unsigned any = __ballot_sync(0xffffffffu, v != 0);
        if (lane == 0) g_is64 = (any == 0u);
    }
    for (int i = cta * NTHR + tid; i < NN; i += ncta * NTHR) g_counts[i] = 0;

    // convert x to fp16 once (25.6 MB -> 12.8 MB), grid-parallel
    {
        const float4* xv = (const float4*)x;
        uint2* xh = (uint2*)g_xh;
        for (int i = cta * NTHR + tid; i < NND / 4; i += ncta * NTHR) {
            float4 v = xv[i];
            __half2 h0 = __floats2half2_rn(v.x, v.y);
            __half2 h1 = __floats2half2_rn(v.z, v.w);
            uint2 u;
            u.x = *(uint32_t*)&h0; u.y = *(uint32_t*)&h1;
            xh[i] = u;
        }
    }

    // ---- stage B = [Wl;Wr] split hi/lo fp16, [n][k] k-contig, stride 272B ----
    {
        int n = tid & 255, kh = tid >> 8;      // kh: 0/1 -> k 0..63 / 64..127
        const float* wrow = ((n < 128) ? (Wl + (size_t)n * DD)
                                       : (Wr + (size_t)(n - 128) * DD)) + kh * 64;
        char* bh = sm + SM_BH + n * RSTR + kh * 128;
        char* blo = sm + SM_BL + n * RSTR + kh * 128;
        #pragma unroll
        for (int u = 0; u < 8; u++) {
            float4 v0 = *(const float4*)(wrow + u * 8);
            float4 v1 = *(const float4*)(wrow + u * 8 + 4);
            uint4 hh, ll;
            split2h(v0.x, v0.y, hh.x, ll.x);
            split2h(v0.z, v0.w, hh.y, ll.y);
            split2h(v1.x, v1.y, hh.z, ll.z);
            split2h(v1.z, v1.w, hh.w, ll.w);
            *(uint4*)(bh + u * 16) = hh;
            *(uint4*)(blo + u * 16) = ll;
        }
    }
    if (tid < 128) bias[tid] = bl[tid];

    grid_barrier(1, ncta);
    const int is64 = g_is64;

    // ---- CSR build on csrn CTAs ----
    if (cta < csrn) {
        const int step = csrn * NTHR;
        const int tg = cta * NTHR + tid;
        for (int e = tg; e < NE; e += step)
            atomicAdd(&g_counts[ld_idx(ei, (long long)NE + e, is64)], 1);
        sub_barrier(1, (unsigned)csrn);
        for (int wb = cta * NTHR + wid * 32; wb < NN; wb += step) {
            int i = wb + lane;
            int c = (i < NN) ? g_counts[i] : 0;
            int s = c;
            #pragma unroll
            for (int off = 1; off < 32; off <<= 1) {
                int v = __shfl_up_sync(0xffffffffu, s, off);
                if (lane >= off) s += v;
            }
            int tot = __shfl_sync(0xffffffffu, s, 31);
            unsigned base = 0;
            if (lane == 31) base = atomicAdd(&g_total, (unsigned)tot);
            base = __shfl_sync(0xffffffffu, base, 31);
            int excl = (int)base + s - c;
            if (i < NN) { g_offsets[i] = excl; g_cursor[i] = excl; }
        }
        sub_barrier(2, (unsigned)csrn);
        for (int e = tg; e < NE; e += step) {
            int src = ld_idx(ei, e, is64);
            int dst = ld_idx(ei, (long long)NE + e, is64);
            int p = atomicAdd(&g_cursor[dst], 1);
            g_srcs[p] = src;
        }
    } else if (do_tail) {
        // ---- tail overlapped with CSR: edge_index passthrough ----
        const int nt2 = ncta - csrn;
        for (int t = (cta - csrn) * NTHR + tid; t < 2 * NE; t += nt2 * NTHR)
            out[NND + t] = (float)ld_idx(ei, t, is64);
    }

    // ---- GEMM: D[128,256] = xh_tile @ [Wl;Wr]^T, 2 B-terms, cp.async dbuf ----
    {
        const int mw = (wid & 3) * 32;
        const int nw = (wid >> 2) * 64;
        const int g = lane >> 3, r = lane & 7;
        const uint32_t aoff = (uint32_t)((mw + r + (g & 1) * 8) * RSTR + (g >> 1) * 16);
        const uint32_t boff = (uint32_t)((nw + r + (g >> 1) * 8) * RSTR + (g & 1) * 16);
        const uint32_t bhb = sb + SM_BH + boff;
        const uint32_t blb = sb + SM_BL + boff;
        const int tr = lane >> 2;
        const int tc = (lane & 3) * 2;

        __syncthreads();
        if (tid == 0) *sm_t = (int)atomicAdd(&g_tile, 1u);
        __syncthreads();
        int t = *sm_t;
        if (t < NT) { stage_a(sb, t * TROWS, 0, tid); CP_COMMIT(); }
        int cur = 0;

        while (t < NT) {
            CP_WAIT0();
            // barrier 1: staged A visible to all warps AND every warp has
            // consumed the previous sm_t value (prevents tile-cursor race)
            __syncthreads();
            if (tid == 0) *sm_t = (int)atomicAdd(&g_tile, 1u);
            __syncthreads();                  // barrier 2: sm_t published
            int tn = *sm_t;
            if (tn < NT) { stage_a(sb, tn * TROWS, 1 ^ cur, tid); CP_COMMIT(); }

            int row0 = t * TROWS;
            uint32_t abase = sb + (cur ? SM_A1 : SM_A0) + aoff;

            float acc[2][8][4];
            #pragma unroll
            for (int mi = 0; mi < 2; mi++)
                #pragma unroll
                for (int ni = 0; ni < 8; ni++)
                    #pragma unroll
                    for (int q = 0; q < 4; q++) acc[mi][ni][q] = 0.f;

            #pragma unroll
            for (int k = 0; k < 8; k++) {
                uint32_t a[2][4], bh[4][4], bl2[4][4];
                ldsm4(a[0], abase + k * 32);
                ldsm4(a[1], abase + 16 * RSTR + k * 32);
                #pragma unroll
                for (int bg = 0; bg < 4; bg++) {
                    ldsm4(bh[bg],  bhb + bg * 16 * RSTR + k * 32);
                    ldsm4(bl2[bg], blb + bg * 16 * RSTR + k * 32);
                }
                #pragma unroll
                for (int mi = 0; mi < 2; mi++)
                    #pragma unroll
                    for (int ni = 0; ni < 8; ni++) {
                        mma_f16(acc[mi][ni], a[mi], &bh[ni >> 1][(ni & 1) * 2]);
                        mma_f16(acc[mi][ni], a[mi], &bl2[ni >> 1][(ni & 1) * 2]);
                    }
            }

            // epilogue: nw<128 -> g_ylh (fp16) ; nw>=128 -> out + bias (f32)
            #pragma unroll
            for (int mi = 0; mi < 2; mi++) {
                #pragma unroll
                for (int rr = 0; rr < 2; rr++) {
                    int row = row0 + mw + mi * 16 + tr + rr * 8;
                    if (row < NN) {
                        if (nw < 128) {
                            __half* dst = g_ylh + (size_t)row * DD + nw + tc;
                            #pragma unroll
                            for (int ni = 0; ni < 8; ni++) {
                                __half2 hv = __floats2half2_rn(
                                    acc[mi][ni][rr * 2], acc[mi][ni][rr * 2 + 1]);
                                *(__half2*)(dst + ni * 8) = hv;
                            }
                        } else {
                            int j0 = nw - 128 + tc;
                            float* dst = out + (size_t)row * DD + j0;
                            #pragma unroll
                            for (int ni = 0; ni < 8; ni++) {
                                float2 v = make_float2(
                                    acc[mi][ni][rr * 2]     + bias[j0 + ni * 8],
                                    acc[mi][ni][rr * 2 + 1] + bias[j0 + ni * 8 + 1]);
                                *(float2*)(dst + ni * 8) = v;
                            }
                        }
                    }
                }
            }
            t = tn; cur ^= 1;
        }
    }

    grid_barrier(2, ncta);

    // ---- aggregate: out = ELU(mean(y_l[src]) + y_r), HALF-warp per node ----
    // 16 lanes x uint4 (8 halfs) cover one 256B y_l row; each warp gathers
    // 2 nodes concurrently (2x MLP). Shuffles use PER-SEGMENT masks: the two
    // half-warps have different trip counts (different node degrees), so a
    // full-warp mask would be a convergence violation (R9/R10 hang).
    {
        const int hw = lane >> 4, hl = lane & 15;
        const unsigned hmask = 0xFFFFu << (hw << 4);
        const uint4* yv = (const uint4*)g_ylh;   // row = 16 uint4
        for (int node = cta * 32 + wid * 2 + hw; node < NN; node += ncta * 32) {
            int start = g_offsets[node];
            int cnt   = g_counts[node];
            float4* orow = (float4*)(out + (size_t)node * DD);
            float4 yr0 = orow[hl * 2];
            float4 yr1 = orow[hl * 2 + 1];
            int m1 = 0, m2 = 0;
            if (hl < cnt)      m1 = g_srcs[start + hl];
            if (hl + 16 < cnt) m2 = g_srcs[start + hl + 16];
            float4 a0 = make_float4(0.f, 0.f, 0.f, 0.f);
            float4 a1 = make_float4(0.f, 0.f, 0.f, 0.f);

#define GACC(u) { \
    float2 p0 = __half22float2(*(__half2*)&(u).x); \
    float2 p1 = __half22float2(*(__half2*)&(u).y); \
    float2 p2 = __half22float2(*(__half2*)&(u).z); \
    float2 p3 = __half22float2(*(__half2*)&(u).w); \
    a0.x += p0.x; a0.y += p0.y; a0.z += p1.x; a0.w += p1.y; \
    a1.x += p2.x; a1.y += p2.y; a1.z += p3.x; a1.w += p3.y; }

            int nb = cnt < 16 ? cnt : 16;
            int j = 0;
            for (; j + 3 < nb; j += 4) {
                int s0 = __shfl_sync(hmask, m1, j,     16);
                int s1 = __shfl_sync(hmask, m1, j + 1, 16);
                int s2 = __shfl_sync(hmask, m1, j + 2, 16);
                int s3 = __shfl_sync(hmask, m1, j + 3, 16);
                uint4 u0 = __ldg(&yv[(size_t)s0 * 16 + hl]);
                uint4 u1 = __ldg(&yv[(size_t)s1 * 16 + hl]);
                uint4 u2 = __ldg(&yv[(size_t)s2 * 16 + hl]);
                uint4 u3 = __ldg(&yv[(size_t)s3 * 16 + hl]);
                GACC(u0); GACC(u1); GACC(u2); GACC(u3);
            }
            for (; j < nb; j++) {
                int s0 = __shfl_sync(hmask, m1, j, 16);
                uint4 u0 = __ldg(&yv[(size_t)s0 * 16 + hl]);
                GACC(u0);
            }
            int nb2 = cnt < 32 ? cnt : 32;
            for (j = 16; j < nb2; j++) {
                int s0 = __shfl_sync(hmask, m2, j - 16, 16);
                uint4 u0 = __ldg(&yv[(size_t)s0 * 16 + hl]);
                GACC(u0);
            }
            for (int i = 32; i < cnt; i++) {        // rare overflow (deg > 32)
                int s0 = g_srcs[start + i];
                uint4 u0 = __ldg(&yv[(size_t)s0 * 16 + hl]);
                GACC(u0);
            }
#undef GACC
            float inv = 1.0f / fmaxf((float)cnt, 1.0f);
            float o0 = a0.x * inv + yr0.x;
            float o1 = a0.y * inv + yr0.y;
            float o2 = a0.z * inv + yr0.z;
            float o3 = a0.w * inv + yr0.w;
            float o4 = a1.x * inv + yr1.x;
            float o5 = a1.y * inv + yr1.y;
            float o6 = a1.z * inv + yr1.z;
            float o7 = a1.w * inv + yr1.w;
            o0 = (o0 > 0.f) ? o0 : expm1f(o0);
            o1 = (o1 > 0.f) ? o1 : expm1f(o1);
            o2 = (o2 > 0.f) ? o2 : expm1f(o2);
            o3 = (o3 > 0.f) ? o3 : expm1f(o3);
            o4 = (o4 > 0.f) ? o4 : expm1f(o4);
            o5 = (o5 > 0.f) ? o5 : expm1f(o5);
            o6 = (o6 > 0.f) ? o6 : expm1f(o6);
            o7 = (o7 > 0.f) ? o7 : expm1f(o7);
            orow[hl * 2]     = make_float4(o0, o1, o2, o3);
            orow[hl * 2 + 1] = make_float4(o4, o5, o6, o7);
        }
    }

    // ---- depart: last CTA out resets all cross-launch state ----
    __syncthreads();
    if (tid == 0) {
        __threadfence();
        unsigned d = atomicAdd(&g_bar_dep, 1u);
        if (d == (unsigned)ncta - 1u) {
            g_bar_cnt = 0; g_bar_phase = 0; g_bar_dep = 0;
            g_sub_cnt = 0; g_sub_phase = 0;
            g_tile = 0;    g_total = 0;
        }
    }
}

// ---------------- launch ----------------
extern "C" void kernel_launch(void* const* d_in, const int* in_sizes, int n_in,
                              void* d_out, int out_size) {
    const float* x  = (const float*)d_in[0];
    const void*  ei = d_in[1];
    const float* Wl = (const float*)d_in[2];
    const float* bl = (const float*)d_in[3];
    const float* Wr = (const float*)d_in[4];
    float* out = (float*)d_out;

    int dev = 0;
    cudaGetDevice(&dev);
    int ncta = 0;
    cudaDeviceGetAttribute(&ncta, cudaDevAttrMultiProcessorCount, dev);
    if (ncta <= 0) ncta = 148;
    int csrn = ncta / 3;
    if (csrn < 1) csrn = 1;
    int do_tail = (out_size >= NND + 2 * NE) ? 1 : 0;

    cudaFuncSetAttribute(k_mega, cudaFuncAttributeMaxDynamicSharedMemorySize,
                         SMEM_BYTES);
    k_mega<<<ncta, NTHR, SMEM_BYTES>>>(x, ei, Wl, bl, Wr, out,
                                       ncta, csrn, do_tail);
}

// round 12
// speedup vs baseline: 1.8075x; 1.0738x over previous
#include <cuda_runtime.h>
#include <cuda_fp16.h>
#include <math.h>
#include <stdint.h>

#define NN 50000
#define NE 600000
#define DD 128
#define NND (NN * DD)
#define TROWS 128
#define NT ((NN + TROWS - 1) / TROWS)   // 391 tiles
#define NTHR 512
#define RSTR 272                         // smem row stride in bytes (17*16)

// ---- smem byte offsets ----
#define SM_BH   0                        // B-hi: 256 rows x 272B
#define SM_BL   69632                    // B-lo
#define SM_A0   139264                   // A buf 0: 128 rows x 272B
#define SM_A1   174080                   // A buf 1
#define SM_BIAS 208896                   // 128 floats
#define SM_T    209408
#define SM_IS64 209412
#define SMEM_BYTES 209424

// ---------------- device scratch ----------------
__device__ int   g_counts[NN];
__device__ int   g_offsets[NN];
__device__ int   g_cursor[NN];
__device__ int   g_srcs[NE];
__device__ __align__(16) __half g_xh[(size_t)(NN + TROWS) * DD]; // fp16(x), padded
__device__ __align__(16) __half g_ylh[(size_t)NN * DD];          // x @ Wl.T fp16
__device__ unsigned g_total   = 0;
__device__ unsigned g_tile    = 0;
__device__ unsigned g_bar_cnt = 0;
__device__ volatile unsigned g_bar_phase = 0;
__device__ unsigned g_bar_dep = 0;
__device__ unsigned g_sub_cnt = 0;               // CSR-group barrier
__device__ volatile unsigned g_sub_phase = 0;
__device__ unsigned g_cvt_cnt = 0;               // GEMM-group (convert) barrier
__device__ volatile unsigned g_cvt_phase = 0;

// ---------------- helpers ----------------
__device__ __forceinline__ uint32_t s2u(const void* p) {
    uint32_t a;
    asm("{ .reg .u64 t; cvta.to.shared.u64 t, %1; cvt.u32.u64 %0, t; }"
        : "=r"(a) : "l"(p));
    return a;
}
__device__ __forceinline__ void ldsm4(uint32_t* r, uint32_t addr) {
    asm volatile("ldmatrix.sync.aligned.m8n8.x4.shared.b16 {%0,%1,%2,%3}, [%4];"
        : "=r"(r[0]), "=r"(r[1]), "=r"(r[2]), "=r"(r[3]) : "r"(addr));
}
__device__ __forceinline__ void mma_f16(float* c, const uint32_t* a,
                                        const uint32_t* b) {
    asm volatile("mma.sync.aligned.m16n8k16.row.col.f32.f16.f16.f32 "
        "{%0,%1,%2,%3}, {%4,%5,%6,%7}, {%8,%9}, {%0,%1,%2,%3};"
        : "+f"(c[0]), "+f"(c[1]), "+f"(c[2]), "+f"(c[3])
        : "r"(a[0]), "r"(a[1]), "r"(a[2]), "r"(a[3]), "r"(b[0]), "r"(b[1]));
}
#define CP_ASYNC16(dst, src) \
    asm volatile("cp.async.cg.shared.global [%0], [%1], 16;" \
                 :: "r"(dst), "l"(src))
#define CP_COMMIT() asm volatile("cp.async.commit_group;" ::: "memory")
#define CP_WAIT0()  asm volatile("cp.async.wait_group 0;"  ::: "memory")

__device__ __forceinline__ int ld_idx(const void* ei, long long pos, int is64) {
    return is64 ? (int)((const long long*)ei)[pos] : ((const int*)ei)[pos];
}
// split 2 consecutive f32 into packed fp16 hi pair + fp16 residual pair
__device__ __forceinline__ void split2h(float f0, float f1, uint32_t& h, uint32_t& l) {
    __half h0 = __float2half_rn(f0);
    __half h1 = __float2half_rn(f1);
    float r0 = f0 - __half2float(h0);
    float r1 = f1 - __half2float(h1);
    __half l0 = __float2half_rn(r0);
    __half l1 = __float2half_rn(r1);
    h = ((uint32_t)__half_as_ushort(h1) << 16) | __half_as_ushort(h0);
    l = ((uint32_t)__half_as_ushort(l1) << 16) | __half_as_ushort(l0);
}

__device__ __forceinline__ void grid_barrier(unsigned use, unsigned ncta) {
    __syncthreads();
    if (threadIdx.x == 0) {
        __threadfence();
        unsigned n = atomicAdd(&g_bar_cnt, 1u);
        if (n == use * ncta - 1u) g_bar_phase = use;
        else while (g_bar_phase < use) __nanosleep(64);
        __threadfence();
    }
    __syncthreads();
}
__device__ __forceinline__ void group_barrier(unsigned* cnt,
                                              volatile unsigned* ph,
                                              unsigned use, unsigned n) {
    __syncthreads();
    if (threadIdx.x == 0) {
        __threadfence();
        unsigned v = atomicAdd(cnt, 1u);
        if (v == use * n - 1u) *ph = use;
        else while (*ph < use) __nanosleep(64);
        __threadfence();
    }
    __syncthreads();
}

// stage one 128-row A tile (fp16, pre-converted) into smem via cp.async
__device__ __forceinline__ void stage_a(uint32_t sb, int row0, int which, int tid) {
    uint32_t ab = sb + (which ? SM_A1 : SM_A0);
    #pragma unroll
    for (int q = 0; q < 4; q++) {
        int c = tid + q * NTHR;          // 0..2047
        int m = c >> 4, ch = c & 15;
        uint32_t dst = ab + m * RSTR + ch * 16;
        const char* src = (const char*)(g_xh + (size_t)(row0 + m) * DD) + ch * 16;
        CP_ASYNC16(dst, src);
    }
}

// ---------------- the persistent mega-kernel ----------------
__global__ void __launch_bounds__(NTHR, 1)
k_mega(const float* __restrict__ x, const void* __restrict__ ei,
       const float* __restrict__ Wl, const float* __restrict__ bl,
       const float* __restrict__ Wr, float* __restrict__ out,
       int ncta, int csrn, int do_tail) {
    extern __shared__ char sm[];
    const uint32_t sb = s2u(sm);
    float* bias = (float*)(sm + SM_BIAS);
    volatile int* sm_t = (volatile int*)(sm + SM_T);

    const int tid  = threadIdx.x;
    const int cta  = blockIdx.x;
    const int wid  = tid >> 5;
    const int lane = tid & 31;
    const int gemn = ncta - csrn;

    // ---- per-CTA init: dtype detect (smem), B staging, bias ----
    if (wid == 0) {
        const int* p = (const int*)ei;
        int v = p[lane * 2 + 1] | p[64 + lane * 2 + 1] |
                p[128 + lane * 2 + 1] | p[192 + lane * 2 + 1];
        unsigned any = __ballot_sync(0xffffffffu, v != 0);
        if (lane == 0) *(volatile int*)(sm + SM_IS64) = (any == 0u);
    }
    // stage B = [Wl;Wr] split hi/lo fp16, [n][k] k-contig, stride 272B
    {
        int n = tid & 255, kh = tid >> 8;      // kh: 0/1 -> k 0..63 / 64..127
        const float* wrow = ((n < 128) ? (Wl + (size_t)n * DD)
                                       : (Wr + (size_t)(n - 128) * DD)) + kh * 64;
        char* bh = sm + SM_BH + n * RSTR + kh * 128;
        char* blo = sm + SM_BL + n * RSTR + kh * 128;
        #pragma unroll
        for (int u = 0; u < 8; u++) {
            float4 v0 = *(const float4*)(wrow + u * 8);
            float4 v1 = *(const float4*)(wrow + u * 8 + 4);
            uint4 hh, ll;
            split2h(v0.x, v0.y, hh.x, ll.x);
            split2h(v0.z, v0.w, hh.y, ll.y);
            split2h(v1.x, v1.y, hh.z, ll.z);
            split2h(v1.z, v1.w, hh.w, ll.w);
            *(uint4*)(bh + u * 16) = hh;
            *(uint4*)(blo + u * 16) = ll;
        }
    }
    if (tid < 128) bias[tid] = bl[tid];
    __syncthreads();
    const int is64 = *(volatile int*)(sm + SM_IS64);

    // ---- CSR group (starts immediately) vs GEMM group (convert+tail) ----
    if (cta < csrn) {
        const int step = csrn * NTHR;
        const int tg = cta * NTHR + tid;
        for (int i = tg; i < NN; i += step) g_counts[i] = 0;
        group_barrier(&g_sub_cnt, &g_sub_phase, 1, (unsigned)csrn);
        for (int e = tg; e < NE; e += step)
            atomicAdd(&g_counts[ld_idx(ei, (long long)NE + e, is64)], 1);
        group_barrier(&g_sub_cnt, &g_sub_phase, 2, (unsigned)csrn);
        for (int wb = cta * NTHR + wid * 32; wb < NN; wb += step) {
            int i = wb + lane;
            int c = (i < NN) ? g_counts[i] : 0;
            int s = c;
            #pragma unroll
            for (int off = 1; off < 32; off <<= 1) {
                int v = __shfl_up_sync(0xffffffffu, s, off);
                if (lane >= off) s += v;
            }
            int tot = __shfl_sync(0xffffffffu, s, 31);
            unsigned base = 0;
            if (lane == 31) base = atomicAdd(&g_total, (unsigned)tot);
            base = __shfl_sync(0xffffffffu, base, 31);
            int excl = (int)base + s - c;
            if (i < NN) { g_offsets[i] = excl; g_cursor[i] = excl; }
        }
        group_barrier(&g_sub_cnt, &g_sub_phase, 3, (unsigned)csrn);
        for (int e = tg; e < NE; e += step) {
            int src = ld_idx(ei, e, is64);
            int dst = ld_idx(ei, (long long)NE + e, is64);
            int p = atomicAdd(&g_cursor[dst], 1);
            g_srcs[p] = src;
        }
        // wait for x->fp16 conversion before joining GEMM tile pool
        if (tid == 0) {
            while (g_cvt_phase < 1u) __nanosleep(64);
            __threadfence();
        }
        __syncthreads();
    } else {
        // convert x to fp16 once, striped over GEMM-group CTAs
        const float4* xv = (const float4*)x;
        uint2* xh = (uint2*)g_xh;
        for (int i = (cta - csrn) * NTHR + tid; i < NND / 4; i += gemn * NTHR) {
            float4 v = xv[i];
            __half2 h0 = __floats2half2_rn(v.x, v.y);
            __half2 h1 = __floats2half2_rn(v.z, v.w);
            uint2 u;
            u.x = *(uint32_t*)&h0; u.y = *(uint32_t*)&h1;
            xh[i] = u;
        }
        group_barrier(&g_cvt_cnt, &g_cvt_phase, 1, (unsigned)gemn);
        if (do_tail) {
            for (int t = (cta - csrn) * NTHR + tid; t < 2 * NE; t += gemn * NTHR)
                out[NND + t] = (float)ld_idx(ei, t, is64);
        }
    }

    // ---- GEMM: D[128,256] = xh_tile @ [Wl;Wr]^T, 2 B-terms, cp.async dbuf ----
    {
        const int mw = (wid & 3) * 32;
        const int nw = (wid >> 2) * 64;
        const int g = lane >> 3, r = lane & 7;
        const uint32_t aoff = (uint32_t)((mw + r + (g & 1) * 8) * RSTR + (g >> 1) * 16);
        const uint32_t boff = (uint32_t)((nw + r + (g >> 1) * 8) * RSTR + (g & 1) * 16);
        const uint32_t bhb = sb + SM_BH + boff;
        const uint32_t blb = sb + SM_BL + boff;
        const int tr = lane >> 2;
        const int tc = (lane & 3) * 2;

        __syncthreads();
        if (tid == 0) *sm_t = (int)atomicAdd(&g_tile, 1u);
        __syncthreads();
        int t = *sm_t;
        if (t < NT) { stage_a(sb, t * TROWS, 0, tid); CP_COMMIT(); }
        int cur = 0;

        while (t < NT) {
            CP_WAIT0();
            // barrier 1: staged A visible to all warps AND every warp has
            // consumed the previous sm_t value (prevents tile-cursor race)
            __syncthreads();
            if (tid == 0) *sm_t = (int)atomicAdd(&g_tile, 1u);
            __syncthreads();                  // barrier 2: sm_t published
            int tn = *sm_t;
            if (tn < NT) { stage_a(sb, tn * TROWS, 1 ^ cur, tid); CP_COMMIT(); }

            int row0 = t * TROWS;
            uint32_t abase = sb + (cur ? SM_A1 : SM_A0) + aoff;

            float acc[2][8][4];
            #pragma unroll
            for (int mi = 0; mi < 2; mi++)
                #pragma unroll
                for (int ni = 0; ni < 8; ni++)
                    #pragma unroll
                    for (int q = 0; q < 4; q++) acc[mi][ni][q] = 0.f;

            #pragma unroll
            for (int k = 0; k < 8; k++) {
                uint32_t a[2][4], bh[4][4], bl2[4][4];
                ldsm4(a[0], abase + k * 32);
                ldsm4(a[1], abase + 16 * RSTR + k * 32);
                #pragma unroll
                for (int bg = 0; bg < 4; bg++) {
                    ldsm4(bh[bg],  bhb + bg * 16 * RSTR + k * 32);
                    ldsm4(bl2[bg], blb + bg * 16 * RSTR + k * 32);
                }
                #pragma unroll
                for (int mi = 0; mi < 2; mi++)
                    #pragma unroll
                    for (int ni = 0; ni < 8; ni++) {
                        mma_f16(acc[mi][ni], a[mi], &bh[ni >> 1][(ni & 1) * 2]);
                        mma_f16(acc[mi][ni], a[mi], &bl2[ni >> 1][(ni & 1) * 2]);
                    }
            }

            // epilogue: nw<128 -> g_ylh (fp16) ; nw>=128 -> out + bias (f32)
            #pragma unroll
            for (int mi = 0; mi < 2; mi++) {
                #pragma unroll
                for (int rr = 0; rr < 2; rr++) {
                    int row = row0 + mw + mi * 16 + tr + rr * 8;
                    if (row < NN) {
                        if (nw < 128) {
                            __half* dst = g_ylh + (size_t)row * DD + nw + tc;
                            #pragma unroll
                            for (int ni = 0; ni < 8; ni++) {
                                __half2 hv = __floats2half2_rn(
                                    acc[mi][ni][rr * 2], acc[mi][ni][rr * 2 + 1]);
                                *(__half2*)(dst + ni * 8) = hv;
                            }
                        } else {
                            int j0 = nw - 128 + tc;
                            float* dst = out + (size_t)row * DD + j0;
                            #pragma unroll
                            for (int ni = 0; ni < 8; ni++) {
                                float2 v = make_float2(
                                    acc[mi][ni][rr * 2]     + bias[j0 + ni * 8],
                                    acc[mi][ni][rr * 2 + 1] + bias[j0 + ni * 8 + 1]);
                                *(float2*)(dst + ni * 8) = v;
                            }
                        }
                    }
                }
            }
            t = tn; cur ^= 1;
        }
    }

    grid_barrier(1, ncta);

    // ---- aggregate: out = ELU(mean(y_l[src]) + y_r), HALF-warp per node ----
    // Per-segment shuffle masks (half-warps have independent trip counts).
    {
        const int hw = lane >> 4, hl = lane & 15;
        const unsigned hmask = 0xFFFFu << (hw << 4);
        const uint4* yv = (const uint4*)g_ylh;   // row = 16 uint4
        for (int node = cta * 32 + wid * 2 + hw; node < NN; node += ncta * 32) {
            int start = g_offsets[node];
            int cnt   = g_counts[node];
            float4* orow = (float4*)(out + (size_t)node * DD);
            float4 yr0 = orow[hl * 2];
            float4 yr1 = orow[hl * 2 + 1];
            int m1 = 0, m2 = 0;
            if (hl < cnt)      m1 = g_srcs[start + hl];
            if (hl + 16 < cnt) m2 = g_srcs[start + hl + 16];
            float4 a0 = make_float4(0.f, 0.f, 0.f, 0.f);
            float4 a1 = make_float4(0.f, 0.f, 0.f, 0.f);

#define GACC(u) { \
    float2 p0 = __half22float2(*(__half2*)&(u).x); \
    float2 p1 = __half22float2(*(__half2*)&(u).y); \
    float2 p2 = __half22float2(*(__half2*)&(u).z); \
    float2 p3 = __half22float2(*(__half2*)&(u).w); \
    a0.x += p0.x; a0.y += p0.y; a0.z += p1.x; a0.w += p1.y; \
    a1.x += p2.x; a1.y += p2.y; a1.z += p3.x; a1.w += p3.y; }

            int nb = cnt < 16 ? cnt : 16;
            int j = 0;
            for (; j + 3 < nb; j += 4) {
                int s0 = __shfl_sync(hmask, m1, j,     16);
                int s1 = __shfl_sync(hmask, m1, j + 1, 16);
                int s2 = __shfl_sync(hmask, m1, j + 2, 16);
                int s3 = __shfl_sync(hmask, m1, j + 3, 16);
                uint4 u0 = __ldg(&yv[(size_t)s0 * 16 + hl]);
                uint4 u1 = __ldg(&yv[(size_t)s1 * 16 + hl]);
                uint4 u2 = __ldg(&yv[(size_t)s2 * 16 + hl]);
                uint4 u3 = __ldg(&yv[(size_t)s3 * 16 + hl]);
                GACC(u0); GACC(u1); GACC(u2); GACC(u3);
            }
            for (; j < nb; j++) {
                int s0 = __shfl_sync(hmask, m1, j, 16);
                uint4 u0 = __ldg(&yv[(size_t)s0 * 16 + hl]);
                GACC(u0);
            }
            int nb2 = cnt < 32 ? cnt : 32;
            for (j = 16; j < nb2; j++) {
                int s0 = __shfl_sync(hmask, m2, j - 16, 16);
                uint4 u0 = __ldg(&yv[(size_t)s0 * 16 + hl]);
                GACC(u0);
            }
            for (int i = 32; i < cnt; i++) {        // rare overflow (deg > 32)
                int s0 = g_srcs[start + i];
                uint4 u0 = __ldg(&yv[(size_t)s0 * 16 + hl]);
                GACC(u0);
            }
#undef GACC
            float inv = 1.0f / fmaxf((float)cnt, 1.0f);
            float o0 = a0.x * inv + yr0.x;
            float o1 = a0.y * inv + yr0.y;
            float o2 = a0.z * inv + yr0.z;
            float o3 = a0.w * inv + yr0.w;
            float o4 = a1.x * inv + yr1.x;
            float o5 = a1.y * inv + yr1.y;
            float o6 = a1.z * inv + yr1.z;
            float o7 = a1.w * inv + yr1.w;
            o0 = (o0 > 0.f) ? o0 : (__expf(o0) - 1.f);
            o1 = (o1 > 0.f) ? o1 : (__expf(o1) - 1.f);
            o2 = (o2 > 0.f) ? o2 : (__expf(o2) - 1.f);
            o3 = (o3 > 0.f) ? o3 : (__expf(o3) - 1.f);
            o4 = (o4 > 0.f) ? o4 : (__expf(o4) - 1.f);
            o5 = (o5 > 0.f) ? o5 : (__expf(o5) - 1.f);
            o6 = (o6 > 0.f) ? o6 : (__expf(o6) - 1.f);
            o7 = (o7 > 0.f) ? o7 : (__expf(o7) - 1.f);
            orow[hl * 2]     = make_float4(o0, o1, o2, o3);
            orow[hl * 2 + 1] = make_float4(o4, o5, o6, o7);
        }
    }

    // ---- depart: last CTA out resets all cross-launch state ----
    __syncthreads();
    if (tid == 0) {
        __threadfence();
        unsigned d = atomicAdd(&g_bar_dep, 1u);
        if (d == (unsigned)ncta - 1u) {
            g_bar_cnt = 0; g_bar_phase = 0; g_bar_dep = 0;
            g_sub_cnt = 0; g_sub_phase = 0;
            g_cvt_cnt = 0; g_cvt_phase = 0;
            g_tile = 0;    g_total = 0;
        }
    }
}

// ---------------- launch ----------------
extern "C" void kernel_launch(void* const* d_in, const int* in_sizes, int n_in,
                              void* d_out, int out_size) {
    const float* x  = (const float*)d_in[0];
    const void*  ei = d_in[1];
    const float* Wl = (const float*)d_in[2];
    const float* bl = (const float*)d_in[3];
    const float* Wr = (const float*)d_in[4];
    float* out = (float*)d_out;

    int dev = 0;
    cudaGetDevice(&dev);
    int ncta = 0;
    cudaDeviceGetAttribute(&ncta, cudaDevAttrMultiProcessorCount, dev);
    if (ncta <= 0) ncta = 148;
    int csrn = ncta / 3;
    if (csrn < 1) csrn = 1;
    int do_tail = (out_size >= NND + 2 * NE) ? 1 : 0;

    cudaFuncSetAttribute(k_mega, cudaFuncAttributeMaxDynamicSharedMemorySize,
                         SMEM_BYTES);
    k_mega<<<ncta, NTHR, SMEM_BYTES>>>(x, ei, Wl, bl, Wr, out,
                                       ncta, csrn, do_tail);
}